// round 2
// baseline (speedup 1.0000x reference)
#include <cuda_runtime.h>

#define NODES 16384
#define BATCH 32
#define F 64
#define DEPTH 15

// Scratch: Y[k][b][a][f], a < NODES>>k, k = 0..14.
// Total ancestors sum_k (16384>>k) = 32767. Size = 32767*32*64 floats = 268 MB.
__device__ float g_Y[(size_t)32767 * BATCH * F];

// -------------------------------------------------------------------------
// Kernel 1: Y_k = X[:, :n_anc] @ W_k^T + b_k  for k = 0..7 (n_anc >= 128).
// Tile: 128 ancestors x 64 outputs per CTA, 128 threads, 8x8 register block.
// smem transposed ([i][row]) so inner-loop reads are LDS.128, conflict-free.
// -------------------------------------------------------------------------
__global__ __launch_bounds__(128) void heap_gemm_big(
    const float* __restrict__ X, const float* __restrict__ W,
    const float* __restrict__ Bv)
{
    __shared__ float Xs[64 * 128];   // [i][a_local], pitch 128 floats
    __shared__ float Ws[64 * 64];    // [i][o],       pitch 64 floats

    // Map blockIdx.x in [0,255) -> (k, a0). Tiles per k: 128>>k.
    int rem = blockIdx.x;
    int k = 0, ntile = 128;
    while (rem >= ntile) { rem -= ntile; ntile >>= 1; ++k; }
    const int a0 = rem * 128;
    const int b  = blockIdx.y;
    const int n_anc = NODES >> k;
    const int tid = threadIdx.x;

    // Load + transpose X tile: rows a0..a0+127. Thread tid owns row r = tid.
    {
        const float4* xg = (const float4*)(X + ((size_t)b * NODES + a0) * F);
        const int r = tid;
        #pragma unroll
        for (int v = 0; v < 16; ++v) {
            float4 q = xg[(size_t)r * 16 + v];
            int i = v * 4;
            Xs[(i + 0) * 128 + r] = q.x;
            Xs[(i + 1) * 128 + r] = q.y;
            Xs[(i + 2) * 128 + r] = q.z;
            Xs[(i + 3) * 128 + r] = q.w;
        }
    }
    // Load + transpose W[k] (64x64). Threads 0..63, thread owns out-row o=tid.
    if (tid < 64) {
        const float4* wg = (const float4*)(W + (size_t)k * F * F + (size_t)tid * F);
        #pragma unroll
        for (int v = 0; v < 16; ++v) {
            float4 q = wg[v];
            int i = v * 4;
            Ws[(i + 0) * 64 + tid] = q.x;
            Ws[(i + 1) * 64 + tid] = q.y;
            Ws[(i + 2) * 64 + tid] = q.z;
            Ws[(i + 3) * 64 + tid] = q.w;
        }
    }
    __syncthreads();

    const int tx = tid & 7;    // o-block: outputs tx*8 .. tx*8+7
    const int ty = tid >> 3;   // a-block: rows    ty*8 .. ty*8+7

    float acc[8][8];
    #pragma unroll
    for (int n = 0; n < 8; ++n) {
        float bb = Bv[k * F + tx * 8 + n];
        #pragma unroll
        for (int m = 0; m < 8; ++m) acc[m][n] = bb;
    }

    const float4* Xs4 = (const float4*)Xs;
    const float4* Ws4 = (const float4*)Ws;

    #pragma unroll 4
    for (int i = 0; i < 64; ++i) {
        float4 x0 = Xs4[i * 32 + ty * 2 + 0];
        float4 x1 = Xs4[i * 32 + ty * 2 + 1];
        float4 w0 = Ws4[i * 16 + tx * 2 + 0];
        float4 w1 = Ws4[i * 16 + tx * 2 + 1];
        float xv[8] = {x0.x, x0.y, x0.z, x0.w, x1.x, x1.y, x1.z, x1.w};
        float wv[8] = {w0.x, w0.y, w0.z, w0.w, w1.x, w1.y, w1.z, w1.w};
        #pragma unroll
        for (int m = 0; m < 8; ++m)
            #pragma unroll
            for (int n = 0; n < 8; ++n)
                acc[m][n] = fmaf(xv[m], wv[n], acc[m][n]);
    }

    const int cum = 32768 - (32768 >> k);          // sum_{k'<k} 16384>>k'
    float* yg = g_Y + (size_t)cum * (BATCH * F)
                    + ((size_t)b * n_anc + a0) * F;
    #pragma unroll
    for (int m = 0; m < 8; ++m) {
        int row = ty * 8 + m;
        float4 s0 = make_float4(acc[m][0], acc[m][1], acc[m][2], acc[m][3]);
        float4 s1 = make_float4(acc[m][4], acc[m][5], acc[m][6], acc[m][7]);
        float4* dst = (float4*)(yg + (size_t)row * F + tx * 8);
        dst[0] = s0;
        dst[1] = s1;
    }
}

// -------------------------------------------------------------------------
// Kernel 2: k = 8..14, tiny ancestor counts (64+32+...+1 = 127 rows).
// One CTA per (pair, batch); 64 threads, one output each.
// -------------------------------------------------------------------------
__global__ __launch_bounds__(64) void heap_gemm_small(
    const float* __restrict__ X, const float* __restrict__ W,
    const float* __restrict__ Bv)
{
    __shared__ float xs[64];
    __shared__ float ws[64 * 65];   // [o][i], pitch 65 -> conflict-free rows

    int rem = blockIdx.x;           // 0..126
    int k = 8, na = 64;
    while (rem >= na) { rem -= na; na >>= 1; ++k; }
    const int a = rem;
    const int b = blockIdx.y;
    const int t = threadIdx.x;
    const int n_anc = NODES >> k;

    xs[t] = X[((size_t)b * NODES + a) * F + t];
    const float* wk = W + (size_t)k * F * F;
    for (int idx = t; idx < F * F; idx += 64)
        ws[(idx >> 6) * 65 + (idx & 63)] = wk[idx];
    __syncthreads();

    float acc = Bv[k * F + t];
    #pragma unroll
    for (int i = 0; i < 64; ++i)
        acc = fmaf(xs[i], ws[t * 65 + i], acc);

    const int cum = 32768 - (32768 >> k);
    g_Y[(size_t)cum * (BATCH * F) + ((size_t)b * n_anc + a) * F + t] = acc;
}

// -------------------------------------------------------------------------
// Kernel 3: gather  out[b,j,:] = sum_{k=0}^{level(j)} Y_k[b, j>>k, :]
// CTA = 64 nodes x 1 batch; thread = (node, 16-float slice). Up to 60
// predicated LDG.128 per thread -> deep MLP; upper-level Y lines are hot
// in L1/L2 (each shared by 2^k nodes).
// -------------------------------------------------------------------------
__global__ __launch_bounds__(256) void heap_gather(float* __restrict__ out)
{
    const int b  = blockIdx.y;
    const int j  = blockIdx.x * 64 + (threadIdx.x >> 2);
    const int fq = (threadIdx.x & 3) * 16;
    const int level = j ? (32 - __clz(j)) : 0;   // bit_length(j)

    float4 a0 = make_float4(0.f, 0.f, 0.f, 0.f);
    float4 a1 = a0, a2 = a0, a3 = a0;

    #pragma unroll
    for (int k = 0; k < DEPTH; ++k) {
        if (level >= k) {
            const int cum = 32768 - (32768 >> k);
            const float4* src = (const float4*)(
                g_Y + (size_t)cum * (BATCH * F)
                    + ((size_t)b * (NODES >> k) + (j >> k)) * F + fq);
            float4 s0 = src[0], s1 = src[1], s2 = src[2], s3 = src[3];
            a0.x += s0.x; a0.y += s0.y; a0.z += s0.z; a0.w += s0.w;
            a1.x += s1.x; a1.y += s1.y; a1.z += s1.z; a1.w += s1.w;
            a2.x += s2.x; a2.y += s2.y; a2.z += s2.z; a2.w += s2.w;
            a3.x += s3.x; a3.y += s3.y; a3.z += s3.z; a3.w += s3.w;
        }
    }

    float4* o = (float4*)(out + ((size_t)b * NODES + j) * F + fq);
    o[0] = a0; o[1] = a1; o[2] = a2; o[3] = a3;
}

// -------------------------------------------------------------------------
extern "C" void kernel_launch(void* const* d_in, const int* in_sizes, int n_in,
                              void* d_out, int out_size) {
    const float* X  = (const float*)d_in[0];   // [32, 16384, 64]
    const float* W  = (const float*)d_in[1];   // [15, 64, 64]
    const float* Bv = (const float*)d_in[2];   // [15, 64]
    float* out = (float*)d_out;                // [32, 16384, 64]

    heap_gemm_big  <<<dim3(255, BATCH), 128>>>(X, W, Bv);
    heap_gemm_small<<<dim3(127, BATCH),  64>>>(X, W, Bv);
    heap_gather    <<<dim3(NODES / 64, BATCH), 256>>>(out);
}

// round 3
// speedup vs baseline: 1.7043x; 1.7043x over previous
#include <cuda_runtime.h>

#define NODES 16384
#define BATCH 32
#define F 64
#define DEPTH 15

typedef unsigned long long ull;

// Chain scratch C_k for k = 1..14 (C_0 goes straight to out).
// Entries: sum_{k=1..14} (NODES>>k) = 16383 rows of [BATCH][64]. ~134 MB.
__device__ float g_C[(size_t)16383 * BATCH * F];

__host__ __device__ constexpr size_t OFF(int k) {
    // row offset of level k within g_C (k >= 1)
    return (size_t)(32768 - (32768 >> k)) - 16384;
}

// ---- f32x2 helpers (FFMA2 path; ptxas only emits FFMA2 from PTX f32x2) ----
__device__ __forceinline__ ull pk2(float a) {
    ull r; asm("mov.b64 %0, {%1, %1};" : "=l"(r) : "f"(a)); return r;
}
__device__ __forceinline__ void ffma2(ull& d, ull a, ull b) {
    asm("fma.rn.f32x2 %0, %1, %2, %0;" : "+l"(d) : "l"(a), "l"(b));
}
__device__ __forceinline__ float2 upk(ull v) {
    float2 r; asm("mov.b64 {%0, %1}, %2;" : "=f"(r.x), "=f"(r.y) : "l"(v)); return r;
}

// -------------------------------------------------------------------------
// Levels 14..8 in one kernel: chain kept in smem, then flushed to g_C.
// One CTA per batch, 256 threads = 4 row-groups x 64 output features.
// -------------------------------------------------------------------------
__global__ __launch_bounds__(256) void heap_chain_small(
    const float* __restrict__ X, const float* __restrict__ W,
    const float* __restrict__ Bv)
{
    __shared__ float ws[64 * 64];     // [i][o] -> conflict-free reads
    __shared__ float cs[127 * 64];    // chain rows, loc(k) = 128 - (1<<(15-k))

    const int b  = blockIdx.x;
    const int t  = threadIdx.x;
    const int o  = t & 63;
    const int rg = t >> 6;            // 0..3

    for (int k = 14; k >= 8; --k) {
        __syncthreads();              // protect ws from previous level's readers
        const float* wk = W + (size_t)k * F * F;
        for (int idx = t; idx < F * F; idx += 256)
            ws[(idx & 63) * 64 + (idx >> 6)] = wk[idx];   // transpose to [i][o]
        __syncthreads();

        const int na     = NODES >> k;
        const int loc    = 128 - (1 << (15 - k));
        const int parloc = 128 - (1 << (14 - k));         // loc(k+1), k<=13

        for (int a = rg; a < na; a += 4) {
            const float* Xb = X + ((size_t)b * NODES + a) * F;
            float s0 = 0.f, s1 = 0.f, s2 = 0.f, s3 = 0.f;
            #pragma unroll
            for (int i = 0; i < 64; i += 4) {
                s0 = fmaf(__ldg(Xb + i + 0), ws[(i + 0) * 64 + o], s0);
                s1 = fmaf(__ldg(Xb + i + 1), ws[(i + 1) * 64 + o], s1);
                s2 = fmaf(__ldg(Xb + i + 2), ws[(i + 2) * 64 + o], s2);
                s3 = fmaf(__ldg(Xb + i + 3), ws[(i + 3) * 64 + o], s3);
            }
            float acc = Bv[k * F + o] + ((s0 + s1) + (s2 + s3));
            if (k < 14) acc += cs[(parloc + (a >> 1)) * 64 + o];
            cs[(loc + a) * 64 + o] = acc;
        }
    }
    __syncthreads();

    // Flush all 127 chain rows (levels 8..14) to global
    for (int k = 8; k <= 14; ++k) {
        const int na  = NODES >> k;
        const int loc = 128 - (1 << (15 - k));
        float* dst = g_C + OFF(k) * (BATCH * F) + (size_t)b * na * F;
        for (int idx = t; idx < na * F; idx += 256)
            dst[idx] = cs[loc * 64 + idx];
    }
}

// -------------------------------------------------------------------------
// Levels 7..0: 128x64 tile GEMM (FFMA2 8x8 register block) + chain epilogue.
//   C_K[a] = X[a] @ W_K^T + b_K + C_{K+1}[a>>1]
//   K==0:  out[j] = C_0[j] - C_{level(j)+1}[b,0]   (level 14 -> no subtract)
// -------------------------------------------------------------------------
template<int K>
__global__ __launch_bounds__(128, 4) void heap_gemm_lvl(
    const float* __restrict__ X, const float* __restrict__ W,
    const float* __restrict__ Bv, float* __restrict__ out)
{
    __shared__ float Xs[64 * 128];   // [i][a_local]
    __shared__ float Ws[64 * 64];    // [i][o]

    const int a0  = blockIdx.x * 128;
    const int b   = blockIdx.y;
    const int tid = threadIdx.x;

    // Load + transpose X tile (row r = tid)
    {
        const float4* xg = (const float4*)(X + ((size_t)b * NODES + a0) * F);
        #pragma unroll
        for (int v = 0; v < 16; ++v) {
            float4 q = xg[(size_t)tid * 16 + v];
            int i = v * 4;
            Xs[(i + 0) * 128 + tid] = q.x;
            Xs[(i + 1) * 128 + tid] = q.y;
            Xs[(i + 2) * 128 + tid] = q.z;
            Xs[(i + 3) * 128 + tid] = q.w;
        }
    }
    if (tid < 64) {
        const float4* wg = (const float4*)(W + (size_t)K * F * F + (size_t)tid * F);
        #pragma unroll
        for (int v = 0; v < 16; ++v) {
            float4 q = wg[v];
            int i = v * 4;
            Ws[(i + 0) * 64 + tid] = q.x;
            Ws[(i + 1) * 64 + tid] = q.y;
            Ws[(i + 2) * 64 + tid] = q.z;
            Ws[(i + 3) * 64 + tid] = q.w;
        }
    }
    __syncthreads();

    const int tx = tid & 7;    // outputs tx*8 .. tx*8+7 (4 f32x2 pairs)
    const int ty = tid >> 3;   // rows    ty*8 .. ty*8+7

    // Bias pairs straight from global (float pair == f32x2 bits)
    ull acc[8][4];
    {
        const ull* bb = (const ull*)(Bv + K * F + tx * 8);
        ull b0 = bb[0], b1 = bb[1], b2 = bb[2], b3 = bb[3];
        #pragma unroll
        for (int m = 0; m < 8; ++m) {
            acc[m][0] = b0; acc[m][1] = b1; acc[m][2] = b2; acc[m][3] = b3;
        }
    }

    const float4* Xs4 = (const float4*)Xs;

    #pragma unroll 4
    for (int i = 0; i < 64; ++i) {
        float4 x0 = Xs4[i * 32 + ty * 2 + 0];
        float4 x1 = Xs4[i * 32 + ty * 2 + 1];
        ulonglong2 w0 = *(const ulonglong2*)(Ws + i * 64 + tx * 8);
        ulonglong2 w1 = *(const ulonglong2*)(Ws + i * 64 + tx * 8 + 4);
        ull wv0 = w0.x, wv1 = w0.y, wv2 = w1.x, wv3 = w1.y;
        ull xx[8];
        xx[0] = pk2(x0.x); xx[1] = pk2(x0.y); xx[2] = pk2(x0.z); xx[3] = pk2(x0.w);
        xx[4] = pk2(x1.x); xx[5] = pk2(x1.y); xx[6] = pk2(x1.z); xx[7] = pk2(x1.w);
        #pragma unroll
        for (int m = 0; m < 8; ++m) {
            ffma2(acc[m][0], xx[m], wv0);
            ffma2(acc[m][1], xx[m], wv1);
            ffma2(acc[m][2], xx[m], wv2);
            ffma2(acc[m][3], xx[m], wv3);
        }
    }

    // Epilogue: add parent chain row, (K==0) subtract root correction, store.
    const size_t BF = (size_t)BATCH * F;
    const float* par = g_C + OFF(K + 1) * BF
                           + (size_t)b * (NODES >> (K + 1)) * F;

    #pragma unroll
    for (int m = 0; m < 8; ++m) {
        const int j = a0 + ty * 8 + m;          // node / ancestor index
        float2 p0 = upk(acc[m][0]), p1 = upk(acc[m][1]);
        float2 p2 = upk(acc[m][2]), p3 = upk(acc[m][3]);

        const float4* pr = (const float4*)(par + (size_t)(j >> 1) * F + tx * 8);
        float4 q0 = pr[0], q1 = pr[1];
        float v0 = p0.x + q0.x, v1 = p0.y + q0.y, v2 = p1.x + q0.z, v3 = p1.y + q0.w;
        float v4 = p2.x + q1.x, v5 = p2.y + q1.y, v6 = p3.x + q1.z, v7 = p3.y + q1.w;

        if (K == 0) {
            const int l = j ? (32 - __clz(j)) : 0;   // bit_length(j) = level
            if (l < 14) {
                const float4* rr = (const float4*)(
                    g_C + OFF(l + 1) * BF + (size_t)b * (NODES >> (l + 1)) * F + tx * 8);
                float4 r0 = rr[0], r1 = rr[1];
                v0 -= r0.x; v1 -= r0.y; v2 -= r0.z; v3 -= r0.w;
                v4 -= r1.x; v5 -= r1.y; v6 -= r1.z; v7 -= r1.w;
            }
            float4* dst = (float4*)(out + ((size_t)b * NODES + j) * F + tx * 8);
            dst[0] = make_float4(v0, v1, v2, v3);
            dst[1] = make_float4(v4, v5, v6, v7);
        } else {
            float* cg = g_C + OFF(K) * BF + ((size_t)b * (NODES >> K) + j) * F;
            float4* dst = (float4*)(cg + tx * 8);
            dst[0] = make_float4(v0, v1, v2, v3);
            dst[1] = make_float4(v4, v5, v6, v7);
        }
    }
}

// -------------------------------------------------------------------------
extern "C" void kernel_launch(void* const* d_in, const int* in_sizes, int n_in,
                              void* d_out, int out_size) {
    const float* X  = (const float*)d_in[0];   // [32, 16384, 64]
    const float* W  = (const float*)d_in[1];   // [15, 64, 64]
    const float* Bv = (const float*)d_in[2];   // [15, 64]
    float* out = (float*)d_out;                // [32, 16384, 64]

    heap_chain_small<<<BATCH, 256>>>(X, W, Bv);
    heap_gemm_lvl<7><<<dim3(  1, BATCH), 128>>>(X, W, Bv, out);
    heap_gemm_lvl<6><<<dim3(  2, BATCH), 128>>>(X, W, Bv, out);
    heap_gemm_lvl<5><<<dim3(  4, BATCH), 128>>>(X, W, Bv, out);
    heap_gemm_lvl<4><<<dim3(  8, BATCH), 128>>>(X, W, Bv, out);
    heap_gemm_lvl<3><<<dim3( 16, BATCH), 128>>>(X, W, Bv, out);
    heap_gemm_lvl<2><<<dim3( 32, BATCH), 128>>>(X, W, Bv, out);
    heap_gemm_lvl<1><<<dim3( 64, BATCH), 128>>>(X, W, Bv, out);
    heap_gemm_lvl<0><<<dim3(128, BATCH), 128>>>(X, W, Bv, out);
}

// round 4
// speedup vs baseline: 1.7186x; 1.0084x over previous
#include <cuda_runtime.h>

#define NODES 16384
#define BATCH 32
#define F 64

typedef unsigned long long ull;

// Y_k for k = 1..14, packed: level k starts at row YOFF(k), n_k = NODES>>k rows.
// Total rows = 16383 -> ~134 MB.
__device__ float g_Y[(size_t)16383 * BATCH * F];
// G[p] = sum_{k'=0}^{level(p)} Y_{k'+1}[p>>k'],  p < 8192. ~67 MB.
__device__ float g_G[(size_t)8192 * BATCH * F];

__host__ __device__ constexpr size_t YOFF(int k) {   // k >= 1
    return (size_t)(16384 - (16384 >> (k - 1)));
}

// ---- f32x2 helpers ----
__device__ __forceinline__ ull pk2(float a) {
    ull r; asm("mov.b64 %0, {%1, %1};" : "=l"(r) : "f"(a)); return r;
}
__device__ __forceinline__ void ffma2(ull& d, ull a, ull b) {
    asm("fma.rn.f32x2 %0, %1, %2, %0;" : "+l"(d) : "l"(a), "l"(b));
}
__device__ __forceinline__ float2 upk(ull v) {
    float2 r; asm("mov.b64 {%0, %1}, %2;" : "=f"(r.x), "=f"(r.y) : "l"(v)); return r;
}

// Shared GEMM tile body: 128 rows x 64 outs, 128 threads, 8x8 FFMA2 block.
// Xg = first row of tile, Wk = 64x64 weights (row-major [o][i]), Bvk = bias.
__device__ __forceinline__ void gemm_tile_body(
    const float* __restrict__ Xg, const float* __restrict__ Wk,
    const float* __restrict__ Bvk, float* Xs, float* Ws,
    ull acc[8][4], int tid)
{
    {   // load + transpose X tile: thread owns row tid
        const float4* xg = (const float4*)Xg;
        #pragma unroll
        for (int v = 0; v < 16; ++v) {
            float4 q = xg[(size_t)tid * 16 + v];
            int i = v * 4;
            Xs[(i + 0) * 128 + tid] = q.x;
            Xs[(i + 1) * 128 + tid] = q.y;
            Xs[(i + 2) * 128 + tid] = q.z;
            Xs[(i + 3) * 128 + tid] = q.w;
        }
    }
    if (tid < 64) {     // load + transpose W to [i][o]
        const float4* wg = (const float4*)(Wk + (size_t)tid * F);
        #pragma unroll
        for (int v = 0; v < 16; ++v) {
            float4 q = wg[v];
            int i = v * 4;
            Ws[(i + 0) * 64 + tid] = q.x;
            Ws[(i + 1) * 64 + tid] = q.y;
            Ws[(i + 2) * 64 + tid] = q.z;
            Ws[(i + 3) * 64 + tid] = q.w;
        }
    }
    __syncthreads();

    const int tx = tid & 7;
    const int ty = tid >> 3;

    {   // bias init (float pair == f32x2 bits)
        const ull* bb = (const ull*)(Bvk + tx * 8);
        ull b0 = bb[0], b1 = bb[1], b2 = bb[2], b3 = bb[3];
        #pragma unroll
        for (int m = 0; m < 8; ++m) {
            acc[m][0] = b0; acc[m][1] = b1; acc[m][2] = b2; acc[m][3] = b3;
        }
    }

    const float4* Xs4 = (const float4*)Xs;
    #pragma unroll 4
    for (int i = 0; i < 64; ++i) {
        float4 x0 = Xs4[i * 32 + ty * 2 + 0];
        float4 x1 = Xs4[i * 32 + ty * 2 + 1];
        ulonglong2 w0 = *(const ulonglong2*)(Ws + i * 64 + tx * 8);
        ulonglong2 w1 = *(const ulonglong2*)(Ws + i * 64 + tx * 8 + 4);
        ull wv0 = w0.x, wv1 = w0.y, wv2 = w1.x, wv3 = w1.y;
        ull xx[8];
        xx[0] = pk2(x0.x); xx[1] = pk2(x0.y); xx[2] = pk2(x0.z); xx[3] = pk2(x0.w);
        xx[4] = pk2(x1.x); xx[5] = pk2(x1.y); xx[6] = pk2(x1.z); xx[7] = pk2(x1.w);
        #pragma unroll
        for (int m = 0; m < 8; ++m) {
            ffma2(acc[m][0], xx[m], wv0);
            ffma2(acc[m][1], xx[m], wv1);
            ffma2(acc[m][2], xx[m], wv2);
            ffma2(acc[m][3], xx[m], wv3);
        }
    }
}

// -------------------------------------------------------------------------
// A: Y_k = X[:, :n_k] @ W_k^T + b_k for k = 1..7. 127 independent tiles.
// -------------------------------------------------------------------------
__global__ __launch_bounds__(128, 4) void heap_gemm_Y(
    const float* __restrict__ X, const float* __restrict__ W,
    const float* __restrict__ Bv)
{
    __shared__ float Xs[64 * 128];
    __shared__ float Ws[64 * 64];

    int rem = blockIdx.x, k = 1, nt = 64;      // tiles per k: 64,32,...,1
    while (rem >= nt) { rem -= nt; nt >>= 1; ++k; }
    const int a0 = rem * 128;
    const int b  = blockIdx.y;
    const int tid = threadIdx.x;
    const int n_k = NODES >> k;

    ull acc[8][4];
    gemm_tile_body(X + ((size_t)b * NODES + a0) * F,
                   W + (size_t)k * F * F, Bv + k * F, Xs, Ws, acc, tid);

    const int tx = tid & 7, ty = tid >> 3;
    float* yg = g_Y + YOFF(k) * (BATCH * F) + ((size_t)b * n_k + a0) * F;
    #pragma unroll
    for (int m = 0; m < 8; ++m) {
        int row = ty * 8 + m;
        float2 p0 = upk(acc[m][0]), p1 = upk(acc[m][1]);
        float2 p2 = upk(acc[m][2]), p3 = upk(acc[m][3]);
        float4* dst = (float4*)(yg + (size_t)row * F + tx * 8);
        dst[0] = make_float4(p0.x, p0.y, p1.x, p1.y);
        dst[1] = make_float4(p2.x, p2.y, p3.x, p3.y);
    }
}

// -------------------------------------------------------------------------
// A': Y_k for k = 8..14 (127 rows total). grid (7, BATCH), 256 threads.
// -------------------------------------------------------------------------
__global__ __launch_bounds__(256) void heap_small_Y(
    const float* __restrict__ X, const float* __restrict__ W,
    const float* __restrict__ Bv)
{
    __shared__ float ws[64 * 64];   // [i][o]

    const int k = 8 + blockIdx.x;
    const int b = blockIdx.y;
    const int t = threadIdx.x;
    const int o = t & 63;
    const int rg = t >> 6;
    const int n = NODES >> k;

    const float* wk = W + (size_t)k * F * F;
    for (int idx = t; idx < F * F; idx += 256)
        ws[(idx & 63) * 64 + (idx >> 6)] = wk[idx];
    __syncthreads();

    float* yg = g_Y + YOFF(k) * (BATCH * F) + (size_t)b * n * F;
    for (int a = rg; a < n; a += 4) {
        const float* Xb = X + ((size_t)b * NODES + a) * F;
        float s0 = 0.f, s1 = 0.f, s2 = 0.f, s3 = 0.f;
        #pragma unroll
        for (int i = 0; i < 64; i += 4) {
            s0 = fmaf(__ldg(Xb + i + 0), ws[(i + 0) * 64 + o], s0);
            s1 = fmaf(__ldg(Xb + i + 1), ws[(i + 1) * 64 + o], s1);
            s2 = fmaf(__ldg(Xb + i + 2), ws[(i + 2) * 64 + o], s2);
            s3 = fmaf(__ldg(Xb + i + 3), ws[(i + 3) * 64 + o], s3);
        }
        yg[(size_t)a * F + o] = Bv[k * F + o] + ((s0 + s1) + (s2 + s3));
    }
}

// -------------------------------------------------------------------------
// B: G[p] = sum_{k'=0}^{level(p)} Y_{k'+1}[p >> k'],  p < 8192.
// Thread = (node, 16-float quarter). Deep predicated LDG.128 chain -> MLP.
// -------------------------------------------------------------------------
__global__ __launch_bounds__(256) void heap_gather_G(void)
{
    const int b  = blockIdx.y;
    const int p  = blockIdx.x * 64 + (threadIdx.x >> 2);
    const int fq = (threadIdx.x & 3) * 16;
    const int level = p ? (32 - __clz(p)) : 0;

    float4 a0 = make_float4(0.f, 0.f, 0.f, 0.f);
    float4 a1 = a0, a2 = a0, a3 = a0;

    #pragma unroll
    for (int kp = 0; kp < 14; ++kp) {
        if (level >= kp) {
            const int kk = kp + 1;
            const float4* src = (const float4*)(
                g_Y + YOFF(kk) * (BATCH * F)
                    + ((size_t)b * (NODES >> kk) + (p >> kp)) * F + fq);
            float4 s0 = src[0], s1 = src[1], s2 = src[2], s3 = src[3];
            a0.x += s0.x; a0.y += s0.y; a0.z += s0.z; a0.w += s0.w;
            a1.x += s1.x; a1.y += s1.y; a1.z += s1.z; a1.w += s1.w;
            a2.x += s2.x; a2.y += s2.y; a2.z += s2.z; a2.w += s2.w;
            a3.x += s3.x; a3.y += s3.y; a3.z += s3.z; a3.w += s3.w;
        }
    }

    float4* o = (float4*)(g_G + ((size_t)b * 8192 + p) * F + fq);
    o[0] = a0; o[1] = a1; o[2] = a2; o[3] = a3;
}

// -------------------------------------------------------------------------
// C: out[j] = X[j] @ W_0^T + b_0 + (j>=1 ? G[j>>1] : 0). Full 16384 nodes.
// -------------------------------------------------------------------------
__global__ __launch_bounds__(128, 4) void heap_gemm_final(
    const float* __restrict__ X, const float* __restrict__ W,
    const float* __restrict__ Bv, float* __restrict__ out)
{
    __shared__ float Xs[64 * 128];
    __shared__ float Ws[64 * 64];

    const int a0  = blockIdx.x * 128;
    const int b   = blockIdx.y;
    const int tid = threadIdx.x;

    ull acc[8][4];
    gemm_tile_body(X + ((size_t)b * NODES + a0) * F, W, Bv, Xs, Ws, acc, tid);

    const int tx = tid & 7, ty = tid >> 3;
    const float* Gb = g_G + (size_t)b * 8192 * F;

    #pragma unroll
    for (int m = 0; m < 8; ++m) {
        const int j = a0 + ty * 8 + m;
        float2 p0 = upk(acc[m][0]), p1 = upk(acc[m][1]);
        float2 p2 = upk(acc[m][2]), p3 = upk(acc[m][3]);
        float v0 = p0.x, v1 = p0.y, v2 = p1.x, v3 = p1.y;
        float v4 = p2.x, v5 = p2.y, v6 = p3.x, v7 = p3.y;

        if (j >= 1) {
            const float4* gr = (const float4*)(Gb + (size_t)(j >> 1) * F + tx * 8);
            float4 q0 = gr[0], q1 = gr[1];
            v0 += q0.x; v1 += q0.y; v2 += q0.z; v3 += q0.w;
            v4 += q1.x; v5 += q1.y; v6 += q1.z; v7 += q1.w;
        }
        float4* dst = (float4*)(out + ((size_t)b * NODES + j) * F + tx * 8);
        dst[0] = make_float4(v0, v1, v2, v3);
        dst[1] = make_float4(v4, v5, v6, v7);
    }
}

// -------------------------------------------------------------------------
extern "C" void kernel_launch(void* const* d_in, const int* in_sizes, int n_in,
                              void* d_out, int out_size) {
    const float* X  = (const float*)d_in[0];   // [32, 16384, 64]
    const float* W  = (const float*)d_in[1];   // [15, 64, 64]
    const float* Bv = (const float*)d_in[2];   // [15, 64]
    float* out = (float*)d_out;                // [32, 16384, 64]

    heap_gemm_Y   <<<dim3(127, BATCH), 128>>>(X, W, Bv);   // k = 1..7 (parallel)
    heap_small_Y  <<<dim3(  7, BATCH), 256>>>(X, W, Bv);   // k = 8..14
    heap_gather_G <<<dim3(128, BATCH), 256>>>();           // G over 8192 nodes
    heap_gemm_final<<<dim3(128, BATCH), 128>>>(X, W, Bv, out);
}

// round 6
// speedup vs baseline: 2.0490x; 1.1923x over previous
#include <cuda_runtime.h>
#include <cuda_bf16.h>
#include <cstdint>

#define NODES 16384
#define BATCH 32
#define F 64

typedef unsigned long long ull;

// Y_k for k=1..14 (level k starts at row YOFF(k)); G[p] for p<8192.
__device__ float g_Y[(size_t)16383 * BATCH * F];
__device__ float g_G[(size_t)8192 * BATCH * F];
// Pre-swizzled SW128 bf16 images of W hi/lo splits: per level 64x64 bf16 = 8KB.
// Layout: row o (64 rows x 128B), byte off = SW128(o*128 + i*2).
__device__ __nv_bfloat16 g_Bhi[15 * 4096];
__device__ __nv_bfloat16 g_Blo[15 * 4096];

__host__ __device__ constexpr size_t YOFF(int k) {   // k >= 1
    return (size_t)(16384 - (16384 >> (k - 1)));
}

#define SW128(x) ((x) ^ (((x) >> 3) & 0x70))

// static smem layout (exactly 48KB)
#define SM_AHI 0            // 128 rows x 128B bf16, SW128   (16 KB)
#define SM_ALO 16384        // 16 KB
#define SM_BHI 32768        // 64 rows x 128B bf16, SW128    (8 KB)
#define SM_BLO 40960        // 8 KB
#define SM_TOTAL 49152

// ---------------- helpers ----------------
__device__ __forceinline__ uint32_t smem_u32(const void* p) {
    uint32_t a;
    asm("{ .reg .u64 t; cvta.to.shared.u64 t, %1; cvt.u32.u64 %0, t; }" : "=r"(a) : "l"(p));
    return a;
}
// pack: low half = lo, high half = hi
__device__ __forceinline__ uint32_t cvt2(float lo, float hi) {
    uint32_t r; asm("cvt.rn.bf16x2.f32 %0, %1, %2;" : "=r"(r) : "f"(hi), "f"(lo)); return r;
}
__device__ __forceinline__ void ldsm4(uint32_t a, uint32_t& r0, uint32_t& r1,
                                      uint32_t& r2, uint32_t& r3) {
    asm volatile("ldmatrix.sync.aligned.m8n8.x4.shared.b16 {%0,%1,%2,%3}, [%4];"
                 : "=r"(r0), "=r"(r1), "=r"(r2), "=r"(r3) : "r"(a));
}
__device__ __forceinline__ void mma16816(float* d, const uint32_t* a,
                                         uint32_t b0, uint32_t b1) {
    asm volatile(
        "mma.sync.aligned.m16n8k16.row.col.f32.bf16.bf16.f32 "
        "{%0,%1,%2,%3}, {%4,%5,%6,%7}, {%8,%9}, {%0,%1,%2,%3};"
        : "+f"(d[0]), "+f"(d[1]), "+f"(d[2]), "+f"(d[3])
        : "r"(a[0]), "r"(a[1]), "r"(a[2]), "r"(a[3]), "r"(b0), "r"(b1));
}

// ---------------------------------------------------------------------------
// Prepass: split W (fp32) into hi/lo bf16, stored PRE-SWIZZLED (SW128 image).
// ---------------------------------------------------------------------------
__global__ void prep_W(const float* __restrict__ W) {
    const int k = blockIdx.x;
    for (int idx = threadIdx.x; idx < 4096; idx += 256) {
        float w = W[k * 4096 + idx];
        __nv_bfloat16 hi = __float2bfloat16(w);
        __nv_bfloat16 lo = __float2bfloat16(w - __bfloat162float(hi));
        int o = idx >> 6, i = idx & 63;
        uint32_t off = SW128((uint32_t)(o * 128 + i * 2));   // byte offset
        g_Bhi[k * 4096 + (off >> 1)] = hi;
        g_Blo[k * 4096 + (off >> 1)] = lo;
    }
}

// ---------------------------------------------------------------------------
// Tile mainloop: D[128x64] = X_tile @ W_k^T, 3-product bf16 split on HMMA.
// 128 threads = 4 warps; warp w owns rows w*32..w*32+31 (2 m16 tiles).
// D[mt][nt][4] fragments per lane (canonical m16n8 f32 layout).
// ---------------------------------------------------------------------------
__device__ __forceinline__ void tc_tile(
    const float* __restrict__ Xg, int k, char* smem, int tid,
    float D[2][8][4])
{
    // ---- A: load fp32 row tid, split hi/lo bf16, store SW128 ----
    {
        const float4* xg = (const float4*)(Xg + (size_t)tid * F);
        #pragma unroll
        for (int v = 0; v < 16; ++v) {
            float4 q = xg[v];
            uint32_t h0 = cvt2(q.x, q.y);
            uint32_t h1 = cvt2(q.z, q.w);
            float r0 = q.x - __uint_as_float(h0 << 16);
            float r1 = q.y - __uint_as_float(h0 & 0xffff0000u);
            float r2 = q.z - __uint_as_float(h1 << 16);
            float r3 = q.w - __uint_as_float(h1 & 0xffff0000u);
            uint32_t l0 = cvt2(r0, r1);
            uint32_t l1 = cvt2(r2, r3);
            uint32_t off = SW128((uint32_t)(tid * 128 + v * 8));
            *(ull*)(smem + SM_AHI + off) = (ull)h0 | ((ull)h1 << 32);
            *(ull*)(smem + SM_ALO + off) = (ull)l0 | ((ull)l1 << 32);
        }
    }
    // ---- B: straight copy of pre-swizzled 8KB images ----
    {
        const uint4* sh = (const uint4*)(g_Bhi + k * 4096);
        const uint4* sl = (const uint4*)(g_Blo + k * 4096);
        uint4* dh = (uint4*)(smem + SM_BHI);
        uint4* dl = (uint4*)(smem + SM_BLO);
        #pragma unroll
        for (int i = 0; i < 4; ++i) {
            dh[tid + 128 * i] = sh[tid + 128 * i];
            dl[tid + 128 * i] = sl[tid + 128 * i];
        }
    }
    __syncthreads();

    #pragma unroll
    for (int mt = 0; mt < 2; ++mt)
        #pragma unroll
        for (int nt = 0; nt < 8; ++nt)
            #pragma unroll
            for (int r = 0; r < 4; ++r) D[mt][nt][r] = 0.f;

    const uint32_t sbase = smem_u32(smem);
    const int w = tid >> 5, l = tid & 31;
    // ldmatrix lane address components (canonical x4 pattern)
    const int arow = w * 32 + ((l >> 3) & 1) * 8 + (l & 7);  // + mt*16
    const int acho = (l >> 4) & 1;                            // chunk offset
    const int brow = ((l >> 4) & 1) * 8 + (l & 7);            // + np*16
    const int bcho = (l >> 3) & 1;

    #pragma unroll
    for (int s = 0; s < 4; ++s) {
        uint32_t ah[2][4], al[2][4];
        #pragma unroll
        for (int mt = 0; mt < 2; ++mt) {
            uint32_t off = SW128((uint32_t)((arow + mt * 16) * 128 + (2 * s + acho) * 16));
            ldsm4(sbase + SM_AHI + off, ah[mt][0], ah[mt][1], ah[mt][2], ah[mt][3]);
            ldsm4(sbase + SM_ALO + off, al[mt][0], al[mt][1], al[mt][2], al[mt][3]);
        }
        #pragma unroll
        for (int np = 0; np < 4; ++np) {   // pairs of n8 tiles
            uint32_t boff = SW128((uint32_t)((np * 16 + brow) * 128 + (2 * s + bcho) * 16));
            uint32_t bh[4], bl[4];
            ldsm4(sbase + SM_BHI + boff, bh[0], bh[1], bh[2], bh[3]);
            ldsm4(sbase + SM_BLO + boff, bl[0], bl[1], bl[2], bl[3]);
            #pragma unroll
            for (int mt = 0; mt < 2; ++mt) {
                mma16816(D[mt][np * 2 + 0], ah[mt], bh[0], bh[1]);
                mma16816(D[mt][np * 2 + 0], al[mt], bh[0], bh[1]);
                mma16816(D[mt][np * 2 + 0], ah[mt], bl[0], bl[1]);
                mma16816(D[mt][np * 2 + 1], ah[mt], bh[2], bh[3]);
                mma16816(D[mt][np * 2 + 1], al[mt], bh[2], bh[3]);
                mma16816(D[mt][np * 2 + 1], ah[mt], bl[2], bl[3]);
            }
        }
    }
    __syncthreads();   // smem reusable after this
}

// ---------------------------------------------------------------------------
// Y producer: bx<127 -> HMMA tile for k=1..7; bx>=127 -> small levels 8..14.
// ---------------------------------------------------------------------------
__global__ __launch_bounds__(128) void heap_tc_Y(
    const float* __restrict__ X, const float* __restrict__ W,
    const float* __restrict__ Bv)
{
    __shared__ char smem[SM_TOTAL];
    const int bx = blockIdx.x, b = blockIdx.y, tid = threadIdx.x;

    if (bx < 127) {
        int rem = bx, k = 1, nt = 64;        // tiles per level: 64,32,...,1
        while (rem >= nt) { rem -= nt; nt >>= 1; ++k; }
        const int a0 = rem * 128;

        float D[2][8][4];
        tc_tile(X + ((size_t)b * NODES + a0) * F, k, smem, tid, D);

        const int w = tid >> 5, l = tid & 31;
        const int g = l >> 2, t2 = (l & 3) * 2;
        const float* bias = Bv + k * F;
        float* yg = g_Y + YOFF(k) * (BATCH * F)
                        + ((size_t)b * (NODES >> k)) * F;
        #pragma unroll
        for (int mt = 0; mt < 2; ++mt) {
            const int r0 = a0 + w * 32 + mt * 16 + g;
            #pragma unroll
            for (int ntl = 0; ntl < 8; ++ntl) {
                const int c = ntl * 8 + t2;
                const float b0 = bias[c], b1 = bias[c + 1];
                *(float2*)(yg + (size_t)r0 * F + c) =
                    make_float2(D[mt][ntl][0] + b0, D[mt][ntl][1] + b1);
                *(float2*)(yg + (size_t)(r0 + 8) * F + c) =
                    make_float2(D[mt][ntl][2] + b0, D[mt][ntl][3] + b1);
            }
        }
    } else {
        // small levels: k = 8..14, fp32 scalar path
        const int k = 8 + (bx - 127);
        const int n = NODES >> k;
        const int o = tid & 63, rg = tid >> 6;           // rg in 0..1
        float* ws = (float*)(smem + SM_AHI);             // [i][o], 16KB
        const float* wk = W + (size_t)k * F * F;
        for (int idx = tid; idx < F * F; idx += 128)
            ws[(idx & 63) * 64 + (idx >> 6)] = wk[idx];
        __syncthreads();

        float* yg = g_Y + YOFF(k) * (BATCH * F) + (size_t)b * n * F;
        for (int a = rg; a < n; a += 2) {
            const float* Xb = X + ((size_t)b * NODES + a) * F;
            float s0 = 0.f, s1 = 0.f, s2 = 0.f, s3 = 0.f;
            #pragma unroll
            for (int i = 0; i < 64; i += 4) {
                s0 = fmaf(__ldg(Xb + i + 0), ws[(i + 0) * 64 + o], s0);
                s1 = fmaf(__ldg(Xb + i + 1), ws[(i + 1) * 64 + o], s1);
                s2 = fmaf(__ldg(Xb + i + 2), ws[(i + 2) * 64 + o], s2);
                s3 = fmaf(__ldg(Xb + i + 3), ws[(i + 3) * 64 + o], s3);
            }
            yg[(size_t)a * F + o] = Bv[k * F + o] + ((s0 + s1) + (s2 + s3));
        }
    }
}

// ---------------------------------------------------------------------------
// Gather: G[p] = sum_{k'=0}^{level(p)} Y_{k'+1}[p >> k'], p < 8192.
// ---------------------------------------------------------------------------
__global__ __launch_bounds__(256) void heap_gather_G(void)
{
    const int b  = blockIdx.y;
    const int p  = blockIdx.x * 64 + (threadIdx.x >> 2);
    const int fq = (threadIdx.x & 3) * 16;
    const int level = p ? (32 - __clz(p)) : 0;

    float4 a0 = make_float4(0.f, 0.f, 0.f, 0.f);
    float4 a1 = a0, a2 = a0, a3 = a0;

    #pragma unroll
    for (int kp = 0; kp < 14; ++kp) {
        if (level >= kp) {
            const int kk = kp + 1;
            const float4* src = (const float4*)(
                g_Y + YOFF(kk) * (BATCH * F)
                    + ((size_t)b * (NODES >> kk) + (p >> kp)) * F + fq);
            float4 s0 = src[0], s1 = src[1], s2 = src[2], s3 = src[3];
            a0.x += s0.x; a0.y += s0.y; a0.z += s0.z; a0.w += s0.w;
            a1.x += s1.x; a1.y += s1.y; a1.z += s1.z; a1.w += s1.w;
            a2.x += s2.x; a2.y += s2.y; a2.z += s2.z; a2.w += s2.w;
            a3.x += s3.x; a3.y += s3.y; a3.z += s3.z; a3.w += s3.w;
        }
    }
    float4* o = (float4*)(g_G + ((size_t)b * 8192 + p) * F + fq);
    o[0] = a0; o[1] = a1; o[2] = a2; o[3] = a3;
}

// ---------------------------------------------------------------------------
// Final: out[j] = X[j] @ W_0^T + b_0 + (j>=1 ? G[j>>1] : 0)
// ---------------------------------------------------------------------------
__global__ __launch_bounds__(128) void heap_tc_final(
    const float* __restrict__ X, const float* __restrict__ W,
    const float* __restrict__ Bv, float* __restrict__ out)
{
    __shared__ char smem[SM_TOTAL];
    const int a0 = blockIdx.x * 128, b = blockIdx.y, tid = threadIdx.x;

    float D[2][8][4];
    tc_tile(X + ((size_t)b * NODES + a0) * F, 0, smem, tid, D);

    const int w = tid >> 5, l = tid & 31;
    const int g = l >> 2, t2 = (l & 3) * 2;
    const float* Gb = g_G + (size_t)b * 8192 * F;
    float* ob = out + (size_t)b * NODES * F;

    #pragma unroll
    for (int mt = 0; mt < 2; ++mt) {
        const int j0 = a0 + w * 32 + mt * 16 + g;
        #pragma unroll
        for (int ntl = 0; ntl < 8; ++ntl) {
            const int c = ntl * 8 + t2;
            const float b0 = Bv[c], b1 = Bv[c + 1];
            {   // row j0
                float v0 = D[mt][ntl][0] + b0, v1 = D[mt][ntl][1] + b1;
                if (j0 >= 1) {
                    float2 gq = *(const float2*)(Gb + (size_t)(j0 >> 1) * F + c);
                    v0 += gq.x; v1 += gq.y;
                }
                *(float2*)(ob + (size_t)j0 * F + c) = make_float2(v0, v1);
            }
            {   // row j0 + 8
                const int j1 = j0 + 8;
                float2 gq = *(const float2*)(Gb + (size_t)(j1 >> 1) * F + c);
                *(float2*)(ob + (size_t)j1 * F + c) =
                    make_float2(D[mt][ntl][2] + b0 + gq.x,
                                D[mt][ntl][3] + b1 + gq.y);
            }
        }
    }
}

// ---------------------------------------------------------------------------
extern "C" void kernel_launch(void* const* d_in, const int* in_sizes, int n_in,
                              void* d_out, int out_size) {
    const float* X  = (const float*)d_in[0];   // [32, 16384, 64]
    const float* W  = (const float*)d_in[1];   // [15, 64, 64]
    const float* Bv = (const float*)d_in[2];   // [15, 64]
    float* out = (float*)d_out;                // [32, 16384, 64]

    prep_W        <<<15, 256>>>(W);
    heap_tc_Y     <<<dim3(134, BATCH), 128>>>(X, W, Bv);
    heap_gather_G <<<dim3(128, BATCH), 256>>>();
    heap_tc_final <<<dim3(128, BATCH), 128>>>(X, W, Bv, out);
}

// round 7
// speedup vs baseline: 2.1076x; 1.0286x over previous
#include <cuda_runtime.h>
#include <cuda_bf16.h>
#include <cstdint>

#define NODES 16384
#define BATCH 32
#define F 64

typedef unsigned long long ull;

// Y_k for k=1..14 (level k starts at row YOFF(k)); G[p] for p<8192.
__device__ float g_Y[(size_t)16383 * BATCH * F];
__device__ float g_G[(size_t)8192 * BATCH * F];
// Pre-swizzled SW128 bf16 images of W hi/lo splits: per level 64x64 bf16 = 8KB.
__device__ __nv_bfloat16 g_Bhi[15 * 4096];
__device__ __nv_bfloat16 g_Blo[15 * 4096];

__host__ __device__ constexpr size_t YOFF(int k) {   // k >= 1
    return (size_t)(16384 - (16384 >> (k - 1)));
}

#define SW128(x) ((x) ^ (((x) >> 3) & 0x70))

// smem: B hi (8KB) + B lo (8KB) = 16KB. (small-level branch reuses as fp32 ws)
#define SM_BHI 0
#define SM_BLO 8192
#define SM_TOTAL 16384

#define YGRID_HMMA 536
#define YGRID      592          // 536 hmma CTAs + 56 small-level CTAs
#define FGRID      592

// ---------------- helpers ----------------
__device__ __forceinline__ uint32_t smem_u32(const void* p) {
    uint32_t a;
    asm("{ .reg .u64 t; cvta.to.shared.u64 t, %1; cvt.u32.u64 %0, t; }" : "=r"(a) : "l"(p));
    return a;
}
// pack: low half = lo, high half = hi
__device__ __forceinline__ uint32_t cvt2(float lo, float hi) {
    uint32_t r; asm("cvt.rn.bf16x2.f32 %0, %1, %2;" : "=r"(r) : "f"(hi), "f"(lo)); return r;
}
__device__ __forceinline__ float lo16f(uint32_t u) { return __uint_as_float(u << 16); }
__device__ __forceinline__ float hi16f(uint32_t u) { return __uint_as_float(u & 0xffff0000u); }

__device__ __forceinline__ void ldsm4(uint32_t a, uint32_t& r0, uint32_t& r1,
                                      uint32_t& r2, uint32_t& r3) {
    asm volatile("ldmatrix.sync.aligned.m8n8.x4.shared.b16 {%0,%1,%2,%3}, [%4];"
                 : "=r"(r0), "=r"(r1), "=r"(r2), "=r"(r3) : "r"(a));
}
__device__ __forceinline__ void mma16816(float* d, const uint32_t* a,
                                         uint32_t b0, uint32_t b1) {
    asm volatile(
        "mma.sync.aligned.m16n8k16.row.col.f32.bf16.bf16.f32 "
        "{%0,%1,%2,%3}, {%4,%5,%6,%7}, {%8,%9}, {%0,%1,%2,%3};"
        : "+f"(d[0]), "+f"(d[1]), "+f"(d[2]), "+f"(d[3])
        : "r"(a[0]), "r"(a[1]), "r"(a[2]), "r"(a[3]), "r"(b0), "r"(b1));
}

// ---------------------------------------------------------------------------
// Prepass: split W (fp32) into hi/lo bf16, stored PRE-SWIZZLED (SW128 image).
// ---------------------------------------------------------------------------
__global__ void prep_W(const float* __restrict__ W) {
    const int k = blockIdx.x;
    for (int idx = threadIdx.x; idx < 4096; idx += 256) {
        float w = W[k * 4096 + idx];
        __nv_bfloat16 hi = __float2bfloat16(w);
        __nv_bfloat16 lo = __float2bfloat16(w - __bfloat162float(hi));
        int o = idx >> 6, i = idx & 63;
        uint32_t off = SW128((uint32_t)(o * 128 + i * 2));   // byte offset
        g_Bhi[k * 4096 + (off >> 1)] = hi;
        g_Blo[k * 4096 + (off >> 1)] = lo;
    }
}

// Copy pre-swizzled B images for level k into smem (128 threads).
__device__ __forceinline__ void load_B(char* smem, int k, int tid) {
    const uint4* sh = (const uint4*)(g_Bhi + k * 4096);
    const uint4* sl = (const uint4*)(g_Blo + k * 4096);
    uint4* dh = (uint4*)(smem + SM_BHI);
    uint4* dl = (uint4*)(smem + SM_BLO);
    #pragma unroll
    for (int i = 0; i < 4; ++i) {
        dh[tid + 128 * i] = sh[tid + 128 * i];
        dl[tid + 128 * i] = sl[tid + 128 * i];
    }
}

// ---------------------------------------------------------------------------
// Tile: D[128x64] = X_tile @ W^T, 3-product bf16 split on HMMA.
// A fragments built DIRECTLY from global (no smem, no syncthreads).
// 4 warps; warp w owns rows w*32..w*32+31 (2 m16 tiles).
// ---------------------------------------------------------------------------
__device__ __forceinline__ void mm_tile(
    const float* __restrict__ Xt,          // X + (b*NODES + a0)*F
    uint32_t sbase, int lane, int warp, float D[2][8][4])
{
    const int g = lane >> 2, t2 = (lane & 3) * 2;
    const int brow = ((lane >> 4) & 1) * 8 + (lane & 7);
    const int bcho = (lane >> 3) & 1;

    #pragma unroll
    for (int mt = 0; mt < 2; ++mt)
        #pragma unroll
        for (int nt = 0; nt < 8; ++nt)
            #pragma unroll
            for (int r = 0; r < 4; ++r) D[mt][nt][r] = 0.f;

    #pragma unroll
    for (int s = 0; s < 4; ++s) {
        uint32_t ah[2][4], al[2][4];
        #pragma unroll
        for (int mt = 0; mt < 2; ++mt) {
            const float* r0 = Xt + (size_t)(warp * 32 + mt * 16 + g) * F + s * 16 + t2;
            const float* r1 = r0 + 8 * F;
            float2 f0 = *(const float2*)(r0);
            float2 f1 = *(const float2*)(r1);
            float2 f2 = *(const float2*)(r0 + 8);
            float2 f3 = *(const float2*)(r1 + 8);
            ah[mt][0] = cvt2(f0.x, f0.y);
            ah[mt][1] = cvt2(f1.x, f1.y);
            ah[mt][2] = cvt2(f2.x, f2.y);
            ah[mt][3] = cvt2(f3.x, f3.y);
            al[mt][0] = cvt2(f0.x - lo16f(ah[mt][0]), f0.y - hi16f(ah[mt][0]));
            al[mt][1] = cvt2(f1.x - lo16f(ah[mt][1]), f1.y - hi16f(ah[mt][1]));
            al[mt][2] = cvt2(f2.x - lo16f(ah[mt][2]), f2.y - hi16f(ah[mt][2]));
            al[mt][3] = cvt2(f3.x - lo16f(ah[mt][3]), f3.y - hi16f(ah[mt][3]));
        }
        #pragma unroll
        for (int np = 0; np < 4; ++np) {
            uint32_t boff = SW128((uint32_t)((np * 16 + brow) * 128 + (2 * s + bcho) * 16));
            uint32_t bh[4], bl[4];
            ldsm4(sbase + SM_BHI + boff, bh[0], bh[1], bh[2], bh[3]);
            ldsm4(sbase + SM_BLO + boff, bl[0], bl[1], bl[2], bl[3]);
            #pragma unroll
            for (int mt = 0; mt < 2; ++mt) {
                mma16816(D[mt][np * 2 + 0], ah[mt], bh[0], bh[1]);
                mma16816(D[mt][np * 2 + 0], al[mt], bh[0], bh[1]);
                mma16816(D[mt][np * 2 + 0], ah[mt], bl[0], bl[1]);
                mma16816(D[mt][np * 2 + 1], ah[mt], bh[2], bh[3]);
                mma16816(D[mt][np * 2 + 1], al[mt], bh[2], bh[3]);
                mma16816(D[mt][np * 2 + 1], ah[mt], bl[2], bl[3]);
            }
        }
    }
}

// ---------------------------------------------------------------------------
// Y producer (persistent): CTAs [0, 536) grid-stride HMMA tiles (k=1..7);
// CTAs [536, 592) handle scalar small levels k=8..14.
// ---------------------------------------------------------------------------
__global__ __launch_bounds__(128) void heap_mm_Y(
    const float* __restrict__ X, const float* __restrict__ W,
    const float* __restrict__ Bv)
{
    __shared__ char smem[SM_TOTAL];
    const int tid = threadIdx.x;
    const int lane = tid & 31, warp = tid >> 5;
    const uint32_t sbase = smem_u32(smem);

    if (blockIdx.x < YGRID_HMMA) {
        int prevk = -1;
        for (int e = blockIdx.x; e < 127 * 32; e += YGRID_HMMA) {
            const int b = e & 31;
            int rem = e >> 5, k = 1, nt = 64;          // tiles/level: 64,32,...,1
            while (rem >= nt) { rem -= nt; nt >>= 1; ++k; }
            const int a0 = rem * 128;

            if (k != prevk) {
                __syncthreads();
                load_B(smem, k, tid);
                __syncthreads();
                prevk = k;
            }

            float D[2][8][4];
            mm_tile(X + ((size_t)b * NODES + a0) * F, sbase, lane, warp, D);

            const int gg = lane >> 2, t2 = (lane & 3) * 2;
            const float* bias = Bv + k * F;
            float* yg = g_Y + YOFF(k) * (BATCH * F) + ((size_t)b * (NODES >> k)) * F;
            #pragma unroll
            for (int mt = 0; mt < 2; ++mt) {
                const int r0 = a0 + warp * 32 + mt * 16 + gg;
                #pragma unroll
                for (int ntl = 0; ntl < 8; ++ntl) {
                    const int c = ntl * 8 + t2;
                    const float b0 = bias[c], b1 = bias[c + 1];
                    *(float2*)(yg + (size_t)r0 * F + c) =
                        make_float2(D[mt][ntl][0] + b0, D[mt][ntl][1] + b1);
                    *(float2*)(yg + (size_t)(r0 + 8) * F + c) =
                        make_float2(D[mt][ntl][2] + b0, D[mt][ntl][3] + b1);
                }
            }
        }
    } else {
        // small levels k = 8..14: 7*32 = 224 jobs over 56 CTAs
        float* ws = (float*)smem;                     // 64x64 fp32 = 16KB
        const int o = tid & 63, rg = tid >> 6;        // rg in 0..1
        int prevk = -1;
        for (int e = blockIdx.x - YGRID_HMMA; e < 224; e += 56) {
            const int k = 8 + (e >> 5);
            const int b = e & 31;
            const int n = NODES >> k;
            if (k != prevk) {
                __syncthreads();
                const float* wk = W + (size_t)k * F * F;
                for (int idx = tid; idx < F * F; idx += 128)
                    ws[(idx & 63) * 64 + (idx >> 6)] = wk[idx];
                __syncthreads();
                prevk = k;
            }
            float* yg = g_Y + YOFF(k) * (BATCH * F) + (size_t)b * n * F;
            for (int a = rg; a < n; a += 2) {
                const float* Xb = X + ((size_t)b * NODES + a) * F;
                float s0 = 0.f, s1 = 0.f, s2 = 0.f, s3 = 0.f;
                #pragma unroll
                for (int i = 0; i < 64; i += 4) {
                    s0 = fmaf(__ldg(Xb + i + 0), ws[(i + 0) * 64 + o], s0);
                    s1 = fmaf(__ldg(Xb + i + 1), ws[(i + 1) * 64 + o], s1);
                    s2 = fmaf(__ldg(Xb + i + 2), ws[(i + 2) * 64 + o], s2);
                    s3 = fmaf(__ldg(Xb + i + 3), ws[(i + 3) * 64 + o], s3);
                }
                yg[(size_t)a * F + o] = Bv[k * F + o] + ((s0 + s1) + (s2 + s3));
            }
        }
    }
}

// ---------------------------------------------------------------------------
// Gather: G[p] = sum_{k'=0}^{level(p)} Y_{k'+1}[p >> k'], p < 8192.
// ---------------------------------------------------------------------------
__global__ __launch_bounds__(256) void heap_gather_G(void)
{
    const int b  = blockIdx.y;
    const int p  = blockIdx.x * 64 + (threadIdx.x >> 2);
    const int fq = (threadIdx.x & 3) * 16;
    const int level = p ? (32 - __clz(p)) : 0;

    float4 a0 = make_float4(0.f, 0.f, 0.f, 0.f);
    float4 a1 = a0, a2 = a0, a3 = a0;

    #pragma unroll
    for (int kp = 0; kp < 14; ++kp) {
        if (level >= kp) {
            const int kk = kp + 1;
            const float4* src = (const float4*)(
                g_Y + YOFF(kk) * (BATCH * F)
                    + ((size_t)b * (NODES >> kk) + (p >> kp)) * F + fq);
            float4 s0 = src[0], s1 = src[1], s2 = src[2], s3 = src[3];
            a0.x += s0.x; a0.y += s0.y; a0.z += s0.z; a0.w += s0.w;
            a1.x += s1.x; a1.y += s1.y; a1.z += s1.z; a1.w += s1.w;
            a2.x += s2.x; a2.y += s2.y; a2.z += s2.z; a2.w += s2.w;
            a3.x += s3.x; a3.y += s3.y; a3.z += s3.z; a3.w += s3.w;
        }
    }
    float4* o = (float4*)(g_G + ((size_t)b * 8192 + p) * F + fq);
    o[0] = a0; o[1] = a1; o[2] = a2; o[3] = a3;
}

// ---------------------------------------------------------------------------
// Final (persistent): out[j] = X[j] @ W_0^T + b_0 + (j>=1 ? G[j>>1] : 0)
// ---------------------------------------------------------------------------
__global__ __launch_bounds__(128) void heap_mm_final(
    const float* __restrict__ X, const float* __restrict__ Bv,
    float* __restrict__ out)
{
    __shared__ char smem[SM_TOTAL];
    const int tid = threadIdx.x;
    const int lane = tid & 31, warp = tid >> 5;
    const uint32_t sbase = smem_u32(smem);

    load_B(smem, 0, tid);
    __syncthreads();

    for (int e = blockIdx.x; e < 128 * 32; e += FGRID) {
        const int b = e & 31;
        const int a0 = (e >> 5) * 128;

        float D[2][8][4];
        mm_tile(X + ((size_t)b * NODES + a0) * F, sbase, lane, warp, D);

        const int gg = lane >> 2, t2 = (lane & 3) * 2;
        const float* Gb = g_G + (size_t)b * 8192 * F;
        float* ob = out + (size_t)b * NODES * F;

        #pragma unroll
        for (int mt = 0; mt < 2; ++mt) {
            const int j0 = a0 + warp * 32 + mt * 16 + gg;
            #pragma unroll
            for (int ntl = 0; ntl < 8; ++ntl) {
                const int c = ntl * 8 + t2;
                const float b0 = Bv[c], b1 = Bv[c + 1];
                {   // row j0
                    float v0 = D[mt][ntl][0] + b0, v1 = D[mt][ntl][1] + b1;
                    if (j0 >= 1) {
                        float2 gq = *(const float2*)(Gb + (size_t)(j0 >> 1) * F + c);
                        v0 += gq.x; v1 += gq.y;
                    }
                    *(float2*)(ob + (size_t)j0 * F + c) = make_float2(v0, v1);
                }
                {   // row j0 + 8
                    const int j1 = j0 + 8;
                    float2 gq = *(const float2*)(Gb + (size_t)(j1 >> 1) * F + c);
                    *(float2*)(ob + (size_t)j1 * F + c) =
                        make_float2(D[mt][ntl][2] + b0 + gq.x,
                                    D[mt][ntl][3] + b1 + gq.y);
                }
            }
        }
    }
}

// ---------------------------------------------------------------------------
extern "C" void kernel_launch(void* const* d_in, const int* in_sizes, int n_in,
                              void* d_out, int out_size) {
    const float* X  = (const float*)d_in[0];   // [32, 16384, 64]
    const float* W  = (const float*)d_in[1];   // [15, 64, 64]
    const float* Bv = (const float*)d_in[2];   // [15, 64]
    float* out = (float*)d_out;                // [32, 16384, 64]

    prep_W        <<<15, 256>>>(W);
    heap_mm_Y     <<<YGRID, 128>>>(X, W, Bv);
    heap_gather_G <<<dim3(128, BATCH), 256>>>();
    heap_mm_final <<<FGRID, 128>>>(X, Bv, out);
}

// round 8
// speedup vs baseline: 2.3888x; 1.1334x over previous
#include <cuda_runtime.h>
#include <cuda_bf16.h>
#include <cstdint>

#define NODES 16384
#define BATCH 32
#define F 64

typedef unsigned long long ull;

// Y_k for k=1..14 (level k starts at row YOFF(k)); G[p] for p<8192.
__device__ float g_Y[(size_t)16383 * BATCH * F];
__device__ float g_G[(size_t)8192 * BATCH * F];
// Pre-swizzled SW128 bf16 images of W hi/lo splits: per level 64x64 bf16 = 8KB.
__device__ __nv_bfloat16 g_Bhi[15 * 4096];
__device__ __nv_bfloat16 g_Blo[15 * 4096];

__host__ __device__ constexpr size_t YOFF(int k) {   // k >= 1
    return (size_t)(16384 - (16384 >> (k - 1)));
}

#define SW128(x) ((x) ^ (((x) >> 3) & 0x70))

// smem: B hi (8KB) + B lo (8KB) = 16KB (small-level branch reuses as fp32 ws)
#define SM_BHI 0
#define SM_BLO 8192
#define SM_TOTAL 16384

#define YGRID_HMMA 296
#define YGRID_SMALL 32
#define YGRID (YGRID_HMMA + YGRID_SMALL)
#define FGRID 296

// ---------------- helpers ----------------
__device__ __forceinline__ uint32_t smem_u32(const void* p) {
    uint32_t a;
    asm("{ .reg .u64 t; cvta.to.shared.u64 t, %1; cvt.u32.u64 %0, t; }" : "=r"(a) : "l"(p));
    return a;
}
// pack: low half = lo, high half = hi
__device__ __forceinline__ uint32_t cvt2(float lo, float hi) {
    uint32_t r; asm("cvt.rn.bf16x2.f32 %0, %1, %2;" : "=r"(r) : "f"(hi), "f"(lo)); return r;
}
__device__ __forceinline__ float lo16f(uint32_t u) { return __uint_as_float(u << 16); }
__device__ __forceinline__ float hi16f(uint32_t u) { return __uint_as_float(u & 0xffff0000u); }

__device__ __forceinline__ void ldsm4(uint32_t a, uint32_t& r0, uint32_t& r1,
                                      uint32_t& r2, uint32_t& r3) {
    asm volatile("ldmatrix.sync.aligned.m8n8.x4.shared.b16 {%0,%1,%2,%3}, [%4];"
                 : "=r"(r0), "=r"(r1), "=r"(r2), "=r"(r3) : "r"(a));
}
__device__ __forceinline__ void mma16816(float* d, const uint32_t* a,
                                         uint32_t b0, uint32_t b1) {
    asm volatile(
        "mma.sync.aligned.m16n8k16.row.col.f32.bf16.bf16.f32 "
        "{%0,%1,%2,%3}, {%4,%5,%6,%7}, {%8,%9}, {%0,%1,%2,%3};"
        : "+f"(d[0]), "+f"(d[1]), "+f"(d[2]), "+f"(d[3])
        : "r"(a[0]), "r"(a[1]), "r"(a[2]), "r"(a[3]), "r"(b0), "r"(b1));
}

// ---------------------------------------------------------------------------
// Prepass: split W (fp32) into hi/lo bf16, stored PRE-SWIZZLED (SW128 image).
// ---------------------------------------------------------------------------
__global__ void prep_W(const float* __restrict__ W) {
    const int k = blockIdx.x;
    for (int idx = threadIdx.x; idx < 4096; idx += 256) {
        float w = W[k * 4096 + idx];
        __nv_bfloat16 hi = __float2bfloat16(w);
        __nv_bfloat16 lo = __float2bfloat16(w - __bfloat162float(hi));
        int o = idx >> 6, i = idx & 63;
        uint32_t off = SW128((uint32_t)(o * 128 + i * 2));   // byte offset
        g_Bhi[k * 4096 + (off >> 1)] = hi;
        g_Blo[k * 4096 + (off >> 1)] = lo;
    }
}

// Copy pre-swizzled B images for level k into smem (256 threads).
__device__ __forceinline__ void load_B(char* smem, int k, int tid) {
    const uint4* sh = (const uint4*)(g_Bhi + k * 4096);
    const uint4* sl = (const uint4*)(g_Blo + k * 4096);
    uint4* dh = (uint4*)(smem + SM_BHI);
    uint4* dl = (uint4*)(smem + SM_BLO);
    #pragma unroll
    for (int i = 0; i < 2; ++i) {
        dh[tid + 256 * i] = sh[tid + 256 * i];
        dl[tid + 256 * i] = sl[tid + 256 * i];
    }
}

// ---------------------------------------------------------------------------
// Tile: D[128x64] = X_tile @ W^T, 3-product bf16 split on HMMA.
// 8 warps, warp owns rows warp*16..warp*16+15 (one m16 tile).
// ALL 16 A-loads (LDG.64) issued up-front -> 4KB in flight per warp.
// ---------------------------------------------------------------------------
__device__ __forceinline__ void mm_tile(
    const float* __restrict__ Xt,          // X + (b*NODES + a0)*F
    uint32_t sbase, int lane, int warp, float D[8][4])
{
    const int g = lane >> 2, t2 = (lane & 3) * 2;
    const int brow = ((lane >> 4) & 1) * 8 + (lane & 7);
    const int bcho = (lane >> 3) & 1;

    // ---- phase 1: issue all A loads (16 x LDG.64 per thread) ----
    float2 f[4][4];                         // [s][quad]
    {
        const float* r0b = Xt + (size_t)(warp * 16 + g) * F + t2;
        const float* r1b = r0b + 8 * F;
        #pragma unroll
        for (int s = 0; s < 4; ++s) {
            f[s][0] = *(const float2*)(r0b + s * 16);
            f[s][1] = *(const float2*)(r1b + s * 16);
            f[s][2] = *(const float2*)(r0b + s * 16 + 8);
            f[s][3] = *(const float2*)(r1b + s * 16 + 8);
        }
    }
    // ---- phase 2: convert to bf16 hi/lo fragments (in place) ----
    uint32_t ah[4][4], al[4][4];
    #pragma unroll
    for (int s = 0; s < 4; ++s)
        #pragma unroll
        for (int q = 0; q < 4; ++q) {
            uint32_t h = cvt2(f[s][q].x, f[s][q].y);
            ah[s][q] = h;
            al[s][q] = cvt2(f[s][q].x - lo16f(h), f[s][q].y - hi16f(h));
        }

    #pragma unroll
    for (int nt = 0; nt < 8; ++nt)
        #pragma unroll
        for (int r = 0; r < 4; ++r) D[nt][r] = 0.f;

    // ---- phase 3: MMA ----
    #pragma unroll
    for (int s = 0; s < 4; ++s) {
        #pragma unroll
        for (int np = 0; np < 4; ++np) {
            uint32_t boff = SW128((uint32_t)((np * 16 + brow) * 128 + (2 * s + bcho) * 16));
            uint32_t bh[4], bl[4];
            ldsm4(sbase + SM_BHI + boff, bh[0], bh[1], bh[2], bh[3]);
            ldsm4(sbase + SM_BLO + boff, bl[0], bl[1], bl[2], bl[3]);
            mma16816(D[np * 2 + 0], ah[s], bh[0], bh[1]);
            mma16816(D[np * 2 + 0], al[s], bh[0], bh[1]);
            mma16816(D[np * 2 + 0], ah[s], bl[0], bl[1]);
            mma16816(D[np * 2 + 1], ah[s], bh[2], bh[3]);
            mma16816(D[np * 2 + 1], al[s], bh[2], bh[3]);
            mma16816(D[np * 2 + 1], ah[s], bl[2], bl[3]);
        }
    }
}

// ---------------------------------------------------------------------------
// Y producer (persistent, block-partitioned): CTAs [0,296) HMMA tiles k=1..7;
// CTAs [296,328) scalar small levels k=8..14.
// ---------------------------------------------------------------------------
__global__ __launch_bounds__(256, 2) void heap_mm_Y(
    const float* __restrict__ X, const float* __restrict__ W,
    const float* __restrict__ Bv)
{
    __shared__ char smem[SM_TOTAL];
    const int tid = threadIdx.x;
    const int lane = tid & 31, warp = tid >> 5;
    const uint32_t sbase = smem_u32(smem);

    if (blockIdx.x < YGRID_HMMA) {
        // block partition of 4064 jobs: chunk = ceil(4064/296) = 14
        const int J = 127 * 32, CH = (J + YGRID_HMMA - 1) / YGRID_HMMA;
        const int e0 = blockIdx.x * CH;
        const int e1 = min(e0 + CH, J);
        int prevk = -1;
        for (int e = e0; e < e1; ++e) {
            const int b = e & 31;
            int rem = e >> 5, k = 1, nt = 64;          // tiles/level: 64,32,...,1
            while (rem >= nt) { rem -= nt; nt >>= 1; ++k; }
            const int a0 = rem * 128;

            if (k != prevk) {
                __syncthreads();
                load_B(smem, k, tid);
                __syncthreads();
                prevk = k;
            }

            float D[8][4];
            mm_tile(X + ((size_t)b * NODES + a0) * F, sbase, lane, warp, D);

            const int gg = lane >> 2, t2 = (lane & 3) * 2;
            const int r0 = a0 + warp * 16 + gg;
            const float* bias = Bv + k * F;
            float* yg = g_Y + YOFF(k) * (BATCH * F) + ((size_t)b * (NODES >> k)) * F;
            #pragma unroll
            for (int ntl = 0; ntl < 8; ++ntl) {
                const int c = ntl * 8 + t2;
                const float b0 = bias[c], b1 = bias[c + 1];
                *(float2*)(yg + (size_t)r0 * F + c) =
                    make_float2(D[ntl][0] + b0, D[ntl][1] + b1);
                *(float2*)(yg + (size_t)(r0 + 8) * F + c) =
                    make_float2(D[ntl][2] + b0, D[ntl][3] + b1);
            }
        }
    } else {
        // small levels k = 8..14: 224 jobs over 32 CTAs (7 each)
        float* ws = (float*)smem;                     // 64x64 fp32 = 16KB
        const int o = tid & 63, rg = tid >> 6;        // rg in 0..3
        const int bx = blockIdx.x - YGRID_HMMA;
        int prevk = -1;
        for (int e = bx * 7; e < min(bx * 7 + 7, 224); ++e) {
            const int k = 8 + (e >> 5);
            const int b = e & 31;
            const int n = NODES >> k;
            if (k != prevk) {
                __syncthreads();
                const float* wk = W + (size_t)k * F * F;
                for (int idx = tid; idx < F * F; idx += 256)
                    ws[(idx & 63) * 64 + (idx >> 6)] = wk[idx];
                __syncthreads();
                prevk = k;
            }
            float* yg = g_Y + YOFF(k) * (BATCH * F) + (size_t)b * n * F;
            for (int a = rg; a < n; a += 4) {
                const float* Xb = X + ((size_t)b * NODES + a) * F;
                float s0 = 0.f, s1 = 0.f, s2 = 0.f, s3 = 0.f;
                #pragma unroll
                for (int i = 0; i < 64; i += 4) {
                    s0 = fmaf(__ldg(Xb + i + 0), ws[(i + 0) * 64 + o], s0);
                    s1 = fmaf(__ldg(Xb + i + 1), ws[(i + 1) * 64 + o], s1);
                    s2 = fmaf(__ldg(Xb + i + 2), ws[(i + 2) * 64 + o], s2);
                    s3 = fmaf(__ldg(Xb + i + 3), ws[(i + 3) * 64 + o], s3);
                }
                yg[(size_t)a * F + o] = Bv[k * F + o] + ((s0 + s1) + (s2 + s3));
            }
        }
    }
}

// ---------------------------------------------------------------------------
// Gather: G[p] = sum_{k'=0}^{level(p)} Y_{k'+1}[p >> k'], p < 8192.
// ---------------------------------------------------------------------------
__global__ __launch_bounds__(256) void heap_gather_G(void)
{
    const int b  = blockIdx.y;
    const int p  = blockIdx.x * 64 + (threadIdx.x >> 2);
    const int fq = (threadIdx.x & 3) * 16;
    const int level = p ? (32 - __clz(p)) : 0;

    float4 a0 = make_float4(0.f, 0.f, 0.f, 0.f);
    float4 a1 = a0, a2 = a0, a3 = a0;

    #pragma unroll
    for (int kp = 0; kp < 14; ++kp) {
        if (level >= kp) {
            const int kk = kp + 1;
            const float4* src = (const float4*)(
                g_Y + YOFF(kk) * (BATCH * F)
                    + ((size_t)b * (NODES >> kk) + (p >> kp)) * F + fq);
            float4 s0 = src[0], s1 = src[1], s2 = src[2], s3 = src[3];
            a0.x += s0.x; a0.y += s0.y; a0.z += s0.z; a0.w += s0.w;
            a1.x += s1.x; a1.y += s1.y; a1.z += s1.z; a1.w += s1.w;
            a2.x += s2.x; a2.y += s2.y; a2.z += s2.z; a2.w += s2.w;
            a3.x += s3.x; a3.y += s3.y; a3.z += s3.z; a3.w += s3.w;
        }
    }
    float4* o = (float4*)(g_G + ((size_t)b * 8192 + p) * F + fq);
    o[0] = a0; o[1] = a1; o[2] = a2; o[3] = a3;
}

// ---------------------------------------------------------------------------
// Final (persistent, block-partitioned):
//   out[j] = X[j] @ W_0^T + b_0 + (j>=1 ? G[j>>1] : 0)
// ---------------------------------------------------------------------------
__global__ __launch_bounds__(256, 2) void heap_mm_final(
    const float* __restrict__ X, const float* __restrict__ Bv,
    float* __restrict__ out)
{
    __shared__ char smem[SM_TOTAL];
    const int tid = threadIdx.x;
    const int lane = tid & 31, warp = tid >> 5;
    const uint32_t sbase = smem_u32(smem);

    load_B(smem, 0, tid);
    __syncthreads();

    const int J = 128 * 32, CH = (J + FGRID - 1) / FGRID;   // 14
    const int e0 = blockIdx.x * CH;
    const int e1 = min(e0 + CH, J);

    for (int e = e0; e < e1; ++e) {
        const int b = e & 31;
        const int a0 = (e >> 5) * 128;

        float D[8][4];
        mm_tile(X + ((size_t)b * NODES + a0) * F, sbase, lane, warp, D);

        const int gg = lane >> 2, t2 = (lane & 3) * 2;
        const int j0 = a0 + warp * 16 + gg;
        const float* Gb = g_G + (size_t)b * 8192 * F;
        float* ob = out + (size_t)b * NODES * F;

        #pragma unroll
        for (int ntl = 0; ntl < 8; ++ntl) {
            const int c = ntl * 8 + t2;
            const float b0 = Bv[c], b1 = Bv[c + 1];
            {   // row j0
                float v0 = D[ntl][0] + b0, v1 = D[ntl][1] + b1;
                if (j0 >= 1) {
                    float2 gq = *(const float2*)(Gb + (size_t)(j0 >> 1) * F + c);
                    v0 += gq.x; v1 += gq.y;
                }
                *(float2*)(ob + (size_t)j0 * F + c) = make_float2(v0, v1);
            }
            {   // row j0 + 8
                const int j1 = j0 + 8;
                float2 gq = *(const float2*)(Gb + (size_t)(j1 >> 1) * F + c);
                *(float2*)(ob + (size_t)j1 * F + c) =
                    make_float2(D[ntl][2] + b0 + gq.x,
                                D[ntl][3] + b1 + gq.y);
            }
        }
    }
}

// ---------------------------------------------------------------------------
extern "C" void kernel_launch(void* const* d_in, const int* in_sizes, int n_in,
                              void* d_out, int out_size) {
    const float* X  = (const float*)d_in[0];   // [32, 16384, 64]
    const float* W  = (const float*)d_in[1];   // [15, 64, 64]
    const float* Bv = (const float*)d_in[2];   // [15, 64]
    float* out = (float*)d_out;                // [32, 16384, 64]

    prep_W        <<<15, 256>>>(W);
    heap_mm_Y     <<<YGRID, 256>>>(X, W, Bv);
    heap_gather_G <<<dim3(128, BATCH), 256>>>();
    heap_mm_final <<<FGRID, 256>>>(X, Bv, out);
}

// round 9
// speedup vs baseline: 2.4327x; 1.0184x over previous
#include <cuda_runtime.h>
#include <cuda_bf16.h>
#include <cstdint>

#define NODES 16384
#define BATCH 32
#define F 64

typedef unsigned long long ull;

// Y_k for k=1..14 (level k starts at row YOFF(k)).
__device__ float g_Y[(size_t)16383 * BATCH * F];
// Pre-swizzled SW128 bf16 images of W hi/lo splits: per level 64x64 bf16 = 8KB.
__device__ __nv_bfloat16 g_Bhi[15 * 4096];
__device__ __nv_bfloat16 g_Blo[15 * 4096];

__host__ __device__ constexpr size_t YOFF(int k) {   // k >= 1
    return (size_t)(16384 - (16384 >> (k - 1)));
}

#define SW128(x) ((x) ^ (((x) >> 3) & 0x70))

// smem: B hi (8KB) + B lo (8KB) = 16KB; final adds Gs (64 x 68 fp32).
#define SM_BHI 0
#define SM_BLO 8192
#define SM_B_TOTAL 16384
#define GS_PITCH 68

#define YGRID_HMMA 296
#define YGRID_SMALL 32
#define YGRID (YGRID_HMMA + YGRID_SMALL)
#define FGRID 296

// ---------------- helpers ----------------
__device__ __forceinline__ uint32_t smem_u32(const void* p) {
    uint32_t a;
    asm("{ .reg .u64 t; cvta.to.shared.u64 t, %1; cvt.u32.u64 %0, t; }" : "=r"(a) : "l"(p));
    return a;
}
// pack: low half = lo, high half = hi
__device__ __forceinline__ uint32_t cvt2(float lo, float hi) {
    uint32_t r; asm("cvt.rn.bf16x2.f32 %0, %1, %2;" : "=r"(r) : "f"(hi), "f"(lo)); return r;
}
__device__ __forceinline__ float lo16f(uint32_t u) { return __uint_as_float(u << 16); }
__device__ __forceinline__ float hi16f(uint32_t u) { return __uint_as_float(u & 0xffff0000u); }

__device__ __forceinline__ void ldsm4(uint32_t a, uint32_t& r0, uint32_t& r1,
                                      uint32_t& r2, uint32_t& r3) {
    asm volatile("ldmatrix.sync.aligned.m8n8.x4.shared.b16 {%0,%1,%2,%3}, [%4];"
                 : "=r"(r0), "=r"(r1), "=r"(r2), "=r"(r3) : "r"(a));
}
__device__ __forceinline__ void mma16816(float* d, const uint32_t* a,
                                         uint32_t b0, uint32_t b1) {
    asm volatile(
        "mma.sync.aligned.m16n8k16.row.col.f32.bf16.bf16.f32 "
        "{%0,%1,%2,%3}, {%4,%5,%6,%7}, {%8,%9}, {%0,%1,%2,%3};"
        : "+f"(d[0]), "+f"(d[1]), "+f"(d[2]), "+f"(d[3])
        : "r"(a[0]), "r"(a[1]), "r"(a[2]), "r"(a[3]), "r"(b0), "r"(b1));
}

// ---------------------------------------------------------------------------
// Prepass: split W (fp32) into hi/lo bf16, stored PRE-SWIZZLED (SW128 image).
// ---------------------------------------------------------------------------
__global__ void prep_W(const float* __restrict__ W) {
    const int k = blockIdx.x;
    for (int idx = threadIdx.x; idx < 4096; idx += 256) {
        float w = W[k * 4096 + idx];
        __nv_bfloat16 hi = __float2bfloat16(w);
        __nv_bfloat16 lo = __float2bfloat16(w - __bfloat162float(hi));
        int o = idx >> 6, i = idx & 63;
        uint32_t off = SW128((uint32_t)(o * 128 + i * 2));   // byte offset
        g_Bhi[k * 4096 + (off >> 1)] = hi;
        g_Blo[k * 4096 + (off >> 1)] = lo;
    }
}

// Copy pre-swizzled B images for level k into smem (256 threads).
__device__ __forceinline__ void load_B(char* smem, int k, int tid) {
    const uint4* sh = (const uint4*)(g_Bhi + k * 4096);
    const uint4* sl = (const uint4*)(g_Blo + k * 4096);
    uint4* dh = (uint4*)(smem + SM_BHI);
    uint4* dl = (uint4*)(smem + SM_BLO);
    #pragma unroll
    for (int i = 0; i < 2; ++i) {
        dh[tid + 256 * i] = sh[tid + 256 * i];
        dl[tid + 256 * i] = sl[tid + 256 * i];
    }
}

// ---------------------------------------------------------------------------
// Tile: D[128x64] = X_tile @ W^T, 3-product bf16 split on HMMA.
// 8 warps, warp owns rows warp*16..warp*16+15; all A loads issued up-front.
// ---------------------------------------------------------------------------
__device__ __forceinline__ void mm_tile(
    const float* __restrict__ Xt, uint32_t sbase, int lane, int warp,
    float D[8][4])
{
    const int g = lane >> 2, t2 = (lane & 3) * 2;
    const int brow = ((lane >> 4) & 1) * 8 + (lane & 7);
    const int bcho = (lane >> 3) & 1;

    float2 f[4][4];
    {
        const float* r0b = Xt + (size_t)(warp * 16 + g) * F + t2;
        const float* r1b = r0b + 8 * F;
        #pragma unroll
        for (int s = 0; s < 4; ++s) {
            f[s][0] = *(const float2*)(r0b + s * 16);
            f[s][1] = *(const float2*)(r1b + s * 16);
            f[s][2] = *(const float2*)(r0b + s * 16 + 8);
            f[s][3] = *(const float2*)(r1b + s * 16 + 8);
        }
    }
    uint32_t ah[4][4], al[4][4];
    #pragma unroll
    for (int s = 0; s < 4; ++s)
        #pragma unroll
        for (int q = 0; q < 4; ++q) {
            uint32_t h = cvt2(f[s][q].x, f[s][q].y);
            ah[s][q] = h;
            al[s][q] = cvt2(f[s][q].x - lo16f(h), f[s][q].y - hi16f(h));
        }

    #pragma unroll
    for (int nt = 0; nt < 8; ++nt)
        #pragma unroll
        for (int r = 0; r < 4; ++r) D[nt][r] = 0.f;

    #pragma unroll
    for (int s = 0; s < 4; ++s) {
        #pragma unroll
        for (int np = 0; np < 4; ++np) {
            uint32_t boff = SW128((uint32_t)((np * 16 + brow) * 128 + (2 * s + bcho) * 16));
            uint32_t bh[4], bl[4];
            ldsm4(sbase + SM_BHI + boff, bh[0], bh[1], bh[2], bh[3]);
            ldsm4(sbase + SM_BLO + boff, bl[0], bl[1], bl[2], bl[3]);
            mma16816(D[np * 2 + 0], ah[s], bh[0], bh[1]);
            mma16816(D[np * 2 + 0], al[s], bh[0], bh[1]);
            mma16816(D[np * 2 + 0], ah[s], bl[0], bl[1]);
            mma16816(D[np * 2 + 1], ah[s], bh[2], bh[3]);
            mma16816(D[np * 2 + 1], al[s], bh[2], bh[3]);
            mma16816(D[np * 2 + 1], ah[s], bl[2], bl[3]);
        }
    }
}

// ---------------------------------------------------------------------------
// Y producer (persistent, block-partitioned): CTAs [0,296) HMMA tiles k=1..7;
// CTAs [296,328) scalar small levels k=8..14.
// ---------------------------------------------------------------------------
__global__ __launch_bounds__(256, 2) void heap_mm_Y(
    const float* __restrict__ X, const float* __restrict__ W,
    const float* __restrict__ Bv)
{
    __shared__ char smem[SM_B_TOTAL];
    const int tid = threadIdx.x;
    const int lane = tid & 31, warp = tid >> 5;
    const uint32_t sbase = smem_u32(smem);

    if (blockIdx.x < YGRID_HMMA) {
        const int J = 127 * 32, CH = (J + YGRID_HMMA - 1) / YGRID_HMMA;  // 14
        const int e0 = blockIdx.x * CH;
        const int e1 = min(e0 + CH, J);
        int prevk = -1;
        for (int e = e0; e < e1; ++e) {
            const int b = e & 31;
            int rem = e >> 5, k = 1, nt = 64;
            while (rem >= nt) { rem -= nt; nt >>= 1; ++k; }
            const int a0 = rem * 128;

            if (k != prevk) {
                __syncthreads();
                load_B(smem, k, tid);
                __syncthreads();
                prevk = k;
            }

            float D[8][4];
            mm_tile(X + ((size_t)b * NODES + a0) * F, sbase, lane, warp, D);

            const int gg = lane >> 2, t2 = (lane & 3) * 2;
            const int r0 = a0 + warp * 16 + gg;
            const float* bias = Bv + k * F;
            float* yg = g_Y + YOFF(k) * (BATCH * F) + ((size_t)b * (NODES >> k)) * F;
            #pragma unroll
            for (int ntl = 0; ntl < 8; ++ntl) {
                const int c = ntl * 8 + t2;
                const float b0 = bias[c], b1 = bias[c + 1];
                *(float2*)(yg + (size_t)r0 * F + c) =
                    make_float2(D[ntl][0] + b0, D[ntl][1] + b1);
                *(float2*)(yg + (size_t)(r0 + 8) * F + c) =
                    make_float2(D[ntl][2] + b0, D[ntl][3] + b1);
            }
        }
    } else {
        // small levels k = 8..14: 224 jobs over 32 CTAs (7 each)
        __shared__ float ws[64 * 64];
        const int o = tid & 63, rg = tid >> 6;
        const int bx = blockIdx.x - YGRID_HMMA;
        int prevk = -1;
        for (int e = bx * 7; e < min(bx * 7 + 7, 224); ++e) {
            const int k = 8 + (e >> 5);
            const int b = e & 31;
            const int n = NODES >> k;
            if (k != prevk) {
                __syncthreads();
                const float* wk = W + (size_t)k * F * F;
                for (int idx = tid; idx < F * F; idx += 256)
                    ws[(idx & 63) * 64 + (idx >> 6)] = wk[idx];
                __syncthreads();
                prevk = k;
            }
            float* yg = g_Y + YOFF(k) * (BATCH * F) + (size_t)b * n * F;
            for (int a = rg; a < n; a += 4) {
                const float* Xb = X + ((size_t)b * NODES + a) * F;
                float s0 = 0.f, s1 = 0.f, s2 = 0.f, s3 = 0.f;
                #pragma unroll
                for (int i = 0; i < 64; i += 4) {
                    s0 = fmaf(__ldg(Xb + i + 0), ws[(i + 0) * 64 + o], s0);
                    s1 = fmaf(__ldg(Xb + i + 1), ws[(i + 1) * 64 + o], s1);
                    s2 = fmaf(__ldg(Xb + i + 2), ws[(i + 2) * 64 + o], s2);
                    s3 = fmaf(__ldg(Xb + i + 3), ws[(i + 3) * 64 + o], s3);
                }
                yg[(size_t)a * F + o] = Bv[k * F + o] + ((s0 + s1) + (s2 + s3));
            }
        }
    }
}

// ---------------------------------------------------------------------------
// Final (persistent, fused gather):
//   Gs[pl] = sum_{kp=0}^{level(p)} Y_{kp+1}[p>>kp]   (p = a0/2 + pl, 64 rows)
//   out[j] = X[j] @ W_0^T + b_0 + (j>=1 ? Gs[(j>>1)-p0] : 0)
// Jobs ordered (b major, tile minor) so a CTA walks consecutive tiles of one
// batch -> upper-level Y rows stay hot in L1/L2 across jobs.
// ---------------------------------------------------------------------------
__global__ __launch_bounds__(256, 2) void heap_mm_final(
    const float* __restrict__ X, const float* __restrict__ Bv,
    float* __restrict__ out)
{
    __shared__ char smem[SM_B_TOTAL];
    __shared__ float Gs[64 * GS_PITCH];
    const int tid = threadIdx.x;
    const int lane = tid & 31, warp = tid >> 5;
    const uint32_t sbase = smem_u32(smem);

    load_B(smem, 0, tid);
    __syncthreads();

    const int J = 128 * 32, CH = (J + FGRID - 1) / FGRID;   // 14
    const int e0 = blockIdx.x * CH;
    const int e1 = min(e0 + CH, J);

    for (int e = e0; e < e1; ++e) {
        const int b = e >> 7;            // batch major
        const int a0 = (e & 127) * 128;  // consecutive tiles within batch
        const int p0 = a0 >> 1;

        // ---- fused gather: 64 G rows into smem ----
        {
            const int pl = tid >> 2;
            const int p = p0 + pl;
            const int fq = (tid & 3) * 16;
            const int level = p ? (32 - __clz((unsigned)p)) : 0;

            float4 a0v = make_float4(0.f, 0.f, 0.f, 0.f);
            float4 a1v = a0v, a2v = a0v, a3v = a0v;
            #pragma unroll
            for (int kp = 0; kp < 14; ++kp) {
                if (level >= kp) {
                    const int kk = kp + 1;
                    const float4* src = (const float4*)(
                        g_Y + YOFF(kk) * (BATCH * F)
                            + ((size_t)b * (NODES >> kk) + (p >> kp)) * F + fq);
                    float4 s0 = src[0], s1 = src[1], s2 = src[2], s3 = src[3];
                    a0v.x += s0.x; a0v.y += s0.y; a0v.z += s0.z; a0v.w += s0.w;
                    a1v.x += s1.x; a1v.y += s1.y; a1v.z += s1.z; a1v.w += s1.w;
                    a2v.x += s2.x; a2v.y += s2.y; a2v.z += s2.z; a2v.w += s2.w;
                    a3v.x += s3.x; a3v.y += s3.y; a3v.z += s3.z; a3v.w += s3.w;
                }
            }
            float4* gd = (float4*)(Gs + pl * GS_PITCH + fq);
            gd[0] = a0v; gd[1] = a1v; gd[2] = a2v; gd[3] = a3v;
        }
        __syncthreads();

        float D[8][4];
        mm_tile(X + ((size_t)b * NODES + a0) * F, sbase, lane, warp, D);

        const int gg = lane >> 2, t2 = (lane & 3) * 2;
        const int j0 = a0 + warp * 16 + gg;
        const int lp0 = (warp * 16 + gg) >> 1;        // Gs row for j0
        const int lp1 = (warp * 16 + gg + 8) >> 1;    // Gs row for j0+8
        float* ob = out + (size_t)b * NODES * F;

        #pragma unroll
        for (int ntl = 0; ntl < 8; ++ntl) {
            const int c = ntl * 8 + t2;
            const float b0 = Bv[c], b1 = Bv[c + 1];
            {   // row j0
                float v0 = D[ntl][0] + b0, v1 = D[ntl][1] + b1;
                if (j0 >= 1) {
                    v0 += Gs[lp0 * GS_PITCH + c];
                    v1 += Gs[lp0 * GS_PITCH + c + 1];
                }
                *(float2*)(ob + (size_t)j0 * F + c) = make_float2(v0, v1);
            }
            {   // row j0 + 8
                *(float2*)(ob + (size_t)(j0 + 8) * F + c) =
                    make_float2(D[ntl][2] + b0 + Gs[lp1 * GS_PITCH + c],
                                D[ntl][3] + b1 + Gs[lp1 * GS_PITCH + c + 1]);
            }
        }
        __syncthreads();   // protect Gs before next job overwrites
    }
}

// ---------------------------------------------------------------------------
extern "C" void kernel_launch(void* const* d_in, const int* in_sizes, int n_in,
                              void* d_out, int out_size) {
    const float* X  = (const float*)d_in[0];   // [32, 16384, 64]
    const float* W  = (const float*)d_in[1];   // [15, 64, 64]
    const float* Bv = (const float*)d_in[2];   // [15, 64]
    float* out = (float*)d_out;                // [32, 16384, 64]

    prep_W        <<<15, 256>>>(W);
    heap_mm_Y     <<<YGRID, 256>>>(X, W, Bv);
    heap_mm_final <<<FGRID, 256>>>(X, Bv, out);
}

// round 10
// speedup vs baseline: 2.8137x; 1.1566x over previous
#include <cuda_runtime.h>
#include <cuda_bf16.h>
#include <cstdint>

#define NODES 16384
#define BATCH 32
#define F 64

typedef unsigned long long ull;

// Y_k for k=2..14 (level k starts at row YOFF(k); k=1 region unused now).
__device__ float g_Y[(size_t)16383 * BATCH * F];

__host__ __device__ constexpr size_t YOFF(int k) {   // k >= 1
    return (size_t)(16384 - (16384 >> (k - 1)));
}

#define SW128(x) ((x) ^ (((x) >> 3) & 0x70))

// Y kernel static smem: B hi/lo
#define SM_BHI 0
#define SM_BLO 8192
#define SM_B_TOTAL 16384

// final kernel dynamic smem layout
#define FB0HI 0
#define FB0LO 8192
#define FB1HI 16384
#define FB1LO 24576
#define FY1S  32768                   // 64 x 68 fp32 = 17408 B
#define FG2S  (32768 + 17408)         // 32 x 68 fp32 = 8704 B
#define SMF_TOTAL (50176 + 8704)      // 58880 B
#define P 68                          // smem row pitch (floats)

#define YGRID_HMMA 296
#define YGRID_SMALL 32
#define YGRID (YGRID_HMMA + YGRID_SMALL)
#define FGRID 296

// ---------------- helpers ----------------
__device__ __forceinline__ uint32_t smem_u32(const void* p) {
    uint32_t a;
    asm("{ .reg .u64 t; cvta.to.shared.u64 t, %1; cvt.u32.u64 %0, t; }" : "=r"(a) : "l"(p));
    return a;
}
// pack: low half = lo, high half = hi
__device__ __forceinline__ uint32_t cvt2(float lo, float hi) {
    uint32_t r; asm("cvt.rn.bf16x2.f32 %0, %1, %2;" : "=r"(r) : "f"(hi), "f"(lo)); return r;
}
__device__ __forceinline__ float lo16f(uint32_t u) { return __uint_as_float(u << 16); }
__device__ __forceinline__ float hi16f(uint32_t u) { return __uint_as_float(u & 0xffff0000u); }

__device__ __forceinline__ void ldsm4(uint32_t a, uint32_t& r0, uint32_t& r1,
                                      uint32_t& r2, uint32_t& r3) {
    asm volatile("ldmatrix.sync.aligned.m8n8.x4.shared.b16 {%0,%1,%2,%3}, [%4];"
                 : "=r"(r0), "=r"(r1), "=r"(r2), "=r"(r3) : "r"(a));
}
__device__ __forceinline__ void mma16816(float* d, const uint32_t* a,
                                         uint32_t b0, uint32_t b1) {
    asm volatile(
        "mma.sync.aligned.m16n8k16.row.col.f32.bf16.bf16.f32 "
        "{%0,%1,%2,%3}, {%4,%5,%6,%7}, {%8,%9}, {%0,%1,%2,%3};"
        : "+f"(d[0]), "+f"(d[1]), "+f"(d[2]), "+f"(d[3])
        : "r"(a[0]), "r"(a[1]), "r"(a[2]), "r"(a[3]), "r"(b0), "r"(b1));
}

// Convert one 64x64 fp32 W level into swizzled bf16 hi/lo smem images.
// 256 threads, each owns 16 elements of one row.
__device__ __forceinline__ void conv_B(const float* __restrict__ Wk,
                                       char* dst_hi, char* dst_lo, int tid) {
    const int o = tid >> 2, i0 = (tid & 3) * 16;
    const float4* wr = (const float4*)(Wk + o * 64 + i0);
    uint32_t h[8], l[8];
    #pragma unroll
    for (int u = 0; u < 4; ++u) {
        float4 q = wr[u];
        uint32_t h0 = cvt2(q.x, q.y);
        uint32_t h1 = cvt2(q.z, q.w);
        h[u * 2 + 0] = h0;
        h[u * 2 + 1] = h1;
        l[u * 2 + 0] = cvt2(q.x - lo16f(h0), q.y - hi16f(h0));
        l[u * 2 + 1] = cvt2(q.z - lo16f(h1), q.w - hi16f(h1));
    }
    uint32_t off0 = SW128((uint32_t)(o * 128 + i0 * 2));
    uint32_t off1 = SW128((uint32_t)(o * 128 + i0 * 2 + 16));
    *(uint4*)(dst_hi + off0) = make_uint4(h[0], h[1], h[2], h[3]);
    *(uint4*)(dst_hi + off1) = make_uint4(h[4], h[5], h[6], h[7]);
    *(uint4*)(dst_lo + off0) = make_uint4(l[0], l[1], l[2], l[3]);
    *(uint4*)(dst_lo + off1) = make_uint4(l[4], l[5], l[6], l[7]);
}

// ---------------------------------------------------------------------------
// Warp-level: D[16 x 64] = Xrow[16 rows] @ W^T via 3-product bf16 split.
// Xrow = X + row0*F for this warp's 16-row group. B images at sb_hi / sb_lo.
// ---------------------------------------------------------------------------
__device__ __forceinline__ void mma_rows16(
    const float* __restrict__ Xrow, uint32_t sb_hi, uint32_t sb_lo,
    int lane, float D[8][4])
{
    const int g = lane >> 2, t2 = (lane & 3) * 2;
    const int brow = ((lane >> 4) & 1) * 8 + (lane & 7);
    const int bcho = (lane >> 3) & 1;

    float2 f[4][4];
    {
        const float* r0b = Xrow + (size_t)g * F + t2;
        const float* r1b = r0b + 8 * F;
        #pragma unroll
        for (int s = 0; s < 4; ++s) {
            f[s][0] = *(const float2*)(r0b + s * 16);
            f[s][1] = *(const float2*)(r1b + s * 16);
            f[s][2] = *(const float2*)(r0b + s * 16 + 8);
            f[s][3] = *(const float2*)(r1b + s * 16 + 8);
        }
    }
    uint32_t ah[4][4], al[4][4];
    #pragma unroll
    for (int s = 0; s < 4; ++s)
        #pragma unroll
        for (int q = 0; q < 4; ++q) {
            uint32_t h = cvt2(f[s][q].x, f[s][q].y);
            ah[s][q] = h;
            al[s][q] = cvt2(f[s][q].x - lo16f(h), f[s][q].y - hi16f(h));
        }

    #pragma unroll
    for (int nt = 0; nt < 8; ++nt)
        #pragma unroll
        for (int r = 0; r < 4; ++r) D[nt][r] = 0.f;

    #pragma unroll
    for (int s = 0; s < 4; ++s) {
        #pragma unroll
        for (int np = 0; np < 4; ++np) {
            uint32_t boff = SW128((uint32_t)((np * 16 + brow) * 128 + (2 * s + bcho) * 16));
            uint32_t bh[4], bl[4];
            ldsm4(sb_hi + boff, bh[0], bh[1], bh[2], bh[3]);
            ldsm4(sb_lo + boff, bl[0], bl[1], bl[2], bl[3]);
            mma16816(D[np * 2 + 0], ah[s], bh[0], bh[1]);
            mma16816(D[np * 2 + 0], al[s], bh[0], bh[1]);
            mma16816(D[np * 2 + 0], ah[s], bl[0], bl[1]);
            mma16816(D[np * 2 + 1], ah[s], bh[2], bh[3]);
            mma16816(D[np * 2 + 1], al[s], bh[2], bh[3]);
            mma16816(D[np * 2 + 1], ah[s], bl[2], bl[3]);
        }
    }
}

// ---------------------------------------------------------------------------
// Y producer (persistent): CTAs [0,296) HMMA tiles k=2..7 (63*32 = 2016 jobs);
// CTAs [296,328) scalar small levels k=8..14.
// ---------------------------------------------------------------------------
__global__ __launch_bounds__(256, 2) void heap_mm_Y(
    const float* __restrict__ X, const float* __restrict__ W,
    const float* __restrict__ Bv)
{
    __shared__ char smem[SM_B_TOTAL];
    const int tid = threadIdx.x;
    const int lane = tid & 31, warp = tid >> 5;
    const uint32_t sbase = smem_u32(smem);

    if (blockIdx.x < YGRID_HMMA) {
        const int J = 63 * 32, CH = (J + YGRID_HMMA - 1) / YGRID_HMMA;  // 7
        const int e0 = blockIdx.x * CH;
        const int e1 = min(e0 + CH, J);
        int prevk = -1;
        for (int e = e0; e < e1; ++e) {
            const int b = e & 31;
            int rem = e >> 5, k = 2, nt = 32;          // tiles/level: 32,16,...,1
            while (rem >= nt) { rem -= nt; nt >>= 1; ++k; }
            const int a0 = rem * 128;

            if (k != prevk) {
                __syncthreads();
                conv_B(W + (size_t)k * F * F, smem + SM_BHI, smem + SM_BLO, tid);
                __syncthreads();
                prevk = k;
            }

            float D[8][4];
            mma_rows16(X + ((size_t)b * NODES + a0 + warp * 16) * F,
                       sbase + SM_BHI, sbase + SM_BLO, lane, D);

            const int gg = lane >> 2, t2 = (lane & 3) * 2;
            const int r0 = a0 + warp * 16 + gg;
            const float* bias = Bv + k * F;
            float* yg = g_Y + YOFF(k) * (BATCH * F) + ((size_t)b * (NODES >> k)) * F;
            #pragma unroll
            for (int ntl = 0; ntl < 8; ++ntl) {
                const int c = ntl * 8 + t2;
                const float b0 = bias[c], b1 = bias[c + 1];
                *(float2*)(yg + (size_t)r0 * F + c) =
                    make_float2(D[ntl][0] + b0, D[ntl][1] + b1);
                *(float2*)(yg + (size_t)(r0 + 8) * F + c) =
                    make_float2(D[ntl][2] + b0, D[ntl][3] + b1);
            }
        }
    } else {
        // small levels k = 8..14: 224 jobs over 32 CTAs (7 each)
        __shared__ float ws[64 * 64];
        const int o = tid & 63, rg = tid >> 6;
        const int bx = blockIdx.x - YGRID_HMMA;
        int prevk = -1;
        for (int e = bx * 7; e < min(bx * 7 + 7, 224); ++e) {
            const int k = 8 + (e >> 5);
            const int b = e & 31;
            const int n = NODES >> k;
            if (k != prevk) {
                __syncthreads();
                const float* wk = W + (size_t)k * F * F;
                for (int idx = tid; idx < F * F; idx += 256)
                    ws[(idx & 63) * 64 + (idx >> 6)] = wk[idx];
                __syncthreads();
                prevk = k;
            }
            float* yg = g_Y + YOFF(k) * (BATCH * F) + (size_t)b * n * F;
            for (int a = rg; a < n; a += 4) {
                const float* Xb = X + ((size_t)b * NODES + a) * F;
                float s0 = 0.f, s1 = 0.f, s2 = 0.f, s3 = 0.f;
                #pragma unroll
                for (int i = 0; i < 64; i += 4) {
                    s0 = fmaf(__ldg(Xb + i + 0), ws[(i + 0) * 64 + o], s0);
                    s1 = fmaf(__ldg(Xb + i + 1), ws[(i + 1) * 64 + o], s1);
                    s2 = fmaf(__ldg(Xb + i + 2), ws[(i + 2) * 64 + o], s2);
                    s3 = fmaf(__ldg(Xb + i + 3), ws[(i + 3) * 64 + o], s3);
                }
                yg[(size_t)a * F + o] = Bv[k * F + o] + ((s0 + s1) + (s2 + s3));
            }
        }
    }
}

// ---------------------------------------------------------------------------
// Final (persistent, Y1 fused + G2 gather warp-specialized):
//   Y1s[pl] = X[p0+pl] @ W_1^T + b_1                 (warps 0-3, HMMA)
//   G2s[ql] = sum_{kp<=level(q)} Y_{kp+2}[q>>kp]     (warps 4-7, gather)
//   out[j]  = X[j] @ W_0^T + b_0
//           + [j>=1]( Y1s[j>>1 - p0] + [j>=2] G2s[j>>2 - q0] )
// ---------------------------------------------------------------------------
__global__ __launch_bounds__(256, 2) void heap_mm_final(
    const float* __restrict__ X, const float* __restrict__ W,
    const float* __restrict__ Bv, float* __restrict__ out)
{
    extern __shared__ char dsm[];
    float* Y1s = (float*)(dsm + FY1S);
    float* G2s = (float*)(dsm + FG2S);
    const int tid = threadIdx.x;
    const int lane = tid & 31, warp = tid >> 5;
    const uint32_t sbase = smem_u32(dsm);

    conv_B(W,        dsm + FB0HI, dsm + FB0LO, tid);
    conv_B(W + 4096, dsm + FB1HI, dsm + FB1LO, tid);

    const int J = 128 * 32, CH = (J + FGRID - 1) / FGRID;   // 14
    const int e0 = blockIdx.x * CH;
    const int e1 = min(e0 + CH, J);

    for (int e = e0; e < e1; ++e) {
        const int b = e >> 7;            // batch major
        const int a0 = (e & 127) * 128;  // consecutive tiles within batch
        const int p0 = a0 >> 1;
        const int q0 = a0 >> 2;

        __syncthreads();   // Y1s/G2s free (prev epilogue done); B images ready

        if (warp < 4) {
            // ---- Y1 tile: rows p0 + warp*16 .. +15 with W1 ----
            float D1[8][4];
            mma_rows16(X + ((size_t)b * NODES + p0 + warp * 16) * F,
                       sbase + FB1HI, sbase + FB1LO, lane, D1);
            const int gg = lane >> 2, t2 = (lane & 3) * 2;
            const int lr = warp * 16 + gg;
            const float* b1v = Bv + F;
            #pragma unroll
            for (int ntl = 0; ntl < 8; ++ntl) {
                const int c = ntl * 8 + t2;
                const float b0 = b1v[c], b1 = b1v[c + 1];
                *(float2*)(Y1s + lr * P + c) =
                    make_float2(D1[ntl][0] + b0, D1[ntl][1] + b1);
                *(float2*)(Y1s + (lr + 8) * P + c) =
                    make_float2(D1[ntl][2] + b0, D1[ntl][3] + b1);
            }
        } else {
            // ---- G2 gather: 32 q rows x 4 quarters over 128 threads ----
            const int t2i = tid - 128;
            const int ql = t2i >> 2;
            const int q = q0 + ql;
            const int fq = (t2i & 3) * 16;
            const int level = q ? (32 - __clz((unsigned)q)) : 0;

            float4 a0v = make_float4(0.f, 0.f, 0.f, 0.f);
            float4 a1v = a0v, a2v = a0v, a3v = a0v;
            #pragma unroll
            for (int kp = 0; kp < 13; ++kp) {
                if (level >= kp) {
                    const int kk = kp + 2;
                    const float4* src = (const float4*)(
                        g_Y + YOFF(kk) * (BATCH * F)
                            + ((size_t)b * (NODES >> kk) + (q >> kp)) * F + fq);
                    float4 s0 = src[0], s1 = src[1], s2 = src[2], s3 = src[3];
                    a0v.x += s0.x; a0v.y += s0.y; a0v.z += s0.z; a0v.w += s0.w;
                    a1v.x += s1.x; a1v.y += s1.y; a1v.z += s1.z; a1v.w += s1.w;
                    a2v.x += s2.x; a2v.y += s2.y; a2v.z += s2.z; a2v.w += s2.w;
                    a3v.x += s3.x; a3v.y += s3.y; a3v.z += s3.z; a3v.w += s3.w;
                }
            }
            float4* gd = (float4*)(G2s + ql * P + fq);
            gd[0] = a0v; gd[1] = a1v; gd[2] = a2v; gd[3] = a3v;
        }

        // ---- main tile with W0 (all warps) ----
        float D0[8][4];
        mma_rows16(X + ((size_t)b * NODES + a0 + warp * 16) * F,
                   sbase + FB0HI, sbase + FB0LO, lane, D0);

        __syncthreads();   // Y1s / G2s complete

        const int gg = lane >> 2, t2 = (lane & 3) * 2;
        const int j0 = a0 + warp * 16 + gg;
        const int lr = warp * 16 + gg;
        const int lp0 = lr >> 1,      lp1 = (lr + 8) >> 1;   // Y1s rows
        const int lq0 = lr >> 2,      lq1 = (lr + 8) >> 2;   // G2s rows
        float* ob = out + (size_t)b * NODES * F;

        #pragma unroll
        for (int ntl = 0; ntl < 8; ++ntl) {
            const int c = ntl * 8 + t2;
            const float b0 = Bv[c], b1 = Bv[c + 1];
            {   // row j0
                float v0 = D0[ntl][0] + b0, v1 = D0[ntl][1] + b1;
                if (j0 >= 1) {
                    v0 += Y1s[lp0 * P + c];
                    v1 += Y1s[lp0 * P + c + 1];
                    if (j0 >= 2) {
                        v0 += G2s[lq0 * P + c];
                        v1 += G2s[lq0 * P + c + 1];
                    }
                }
                *(float2*)(ob + (size_t)j0 * F + c) = make_float2(v0, v1);
            }
            {   // row j0 + 8 (always >= 8, both terms apply)
                *(float2*)(ob + (size_t)(j0 + 8) * F + c) =
                    make_float2(D0[ntl][2] + b0 + Y1s[lp1 * P + c] + G2s[lq1 * P + c],
                                D0[ntl][3] + b1 + Y1s[lp1 * P + c + 1] + G2s[lq1 * P + c + 1]);
            }
        }
    }
}

// ---------------------------------------------------------------------------
extern "C" void kernel_launch(void* const* d_in, const int* in_sizes, int n_in,
                              void* d_out, int out_size) {
    const float* X  = (const float*)d_in[0];   // [32, 16384, 64]
    const float* W  = (const float*)d_in[1];   // [15, 64, 64]
    const float* Bv = (const float*)d_in[2];   // [15, 64]
    float* out = (float*)d_out;                // [32, 16384, 64]

    cudaFuncSetAttribute(heap_mm_final,
                         cudaFuncAttributeMaxDynamicSharedMemorySize, SMF_TOTAL);

    heap_mm_Y     <<<YGRID, 256>>>(X, W, Bv);
    heap_mm_final <<<FGRID, 256, SMF_TOTAL>>>(X, W, Bv, out);
}

// round 11
// speedup vs baseline: 2.9755x; 1.0575x over previous
#include <cuda_runtime.h>
#include <cuda_bf16.h>
#include <cstdint>

#define NODES 16384
#define BATCH 32
#define F 64

typedef unsigned long long ull;

// Y_k for k=3..14 (level k starts at row YOFF(k); k<3 regions unused).
__device__ float g_Y[(size_t)16383 * BATCH * F];

__host__ __device__ constexpr size_t YOFF(int k) {   // k >= 1
    return (size_t)(16384 - (16384 >> (k - 1)));
}

#define SW128(x) ((x) ^ (((x) >> 3) & 0x70))

// Y kernel static smem: B hi/lo
#define SM_BHI 0
#define SM_BLO 8192
#define SM_B_TOTAL 16384

// final kernel dynamic smem layout
#define FB0HI 0
#define FB0LO 8192
#define FB1HI 16384
#define FB1LO 24576
#define FB2HI 32768
#define FB2LO 40960
#define FY1S  49152                        // 64 x 68 fp32 = 17408 B
#define FY2S  (49152 + 17408)              // 32 x 68 fp32 =  8704 B
#define FG3S  (49152 + 17408 + 8704)       // 16 x 68 fp32 =  4352 B
#define SMF_TOTAL (49152 + 17408 + 8704 + 4352)   // 79616 B
#define P 68                               // smem row pitch (floats)

#define YGRID_HMMA 296
#define YGRID_SMALL 32
#define YGRID (YGRID_HMMA + YGRID_SMALL)
#define FGRID 296

// ---------------- helpers ----------------
__device__ __forceinline__ uint32_t smem_u32(const void* p) {
    uint32_t a;
    asm("{ .reg .u64 t; cvta.to.shared.u64 t, %1; cvt.u32.u64 %0, t; }" : "=r"(a) : "l"(p));
    return a;
}
// pack: low half = lo, high half = hi
__device__ __forceinline__ uint32_t cvt2(float lo, float hi) {
    uint32_t r; asm("cvt.rn.bf16x2.f32 %0, %1, %2;" : "=r"(r) : "f"(hi), "f"(lo)); return r;
}
__device__ __forceinline__ float lo16f(uint32_t u) { return __uint_as_float(u << 16); }
__device__ __forceinline__ float hi16f(uint32_t u) { return __uint_as_float(u & 0xffff0000u); }

__device__ __forceinline__ void ldsm4(uint32_t a, uint32_t& r0, uint32_t& r1,
                                      uint32_t& r2, uint32_t& r3) {
    asm volatile("ldmatrix.sync.aligned.m8n8.x4.shared.b16 {%0,%1,%2,%3}, [%4];"
                 : "=r"(r0), "=r"(r1), "=r"(r2), "=r"(r3) : "r"(a));
}
__device__ __forceinline__ void mma16816(float* d, const uint32_t* a,
                                         uint32_t b0, uint32_t b1) {
    asm volatile(
        "mma.sync.aligned.m16n8k16.row.col.f32.bf16.bf16.f32 "
        "{%0,%1,%2,%3}, {%4,%5,%6,%7}, {%8,%9}, {%0,%1,%2,%3};"
        : "+f"(d[0]), "+f"(d[1]), "+f"(d[2]), "+f"(d[3])
        : "r"(a[0]), "r"(a[1]), "r"(a[2]), "r"(a[3]), "r"(b0), "r"(b1));
}

// Convert one 64x64 fp32 W level into swizzled bf16 hi/lo smem images.
// 256 threads, each owns 16 elements of one row.
__device__ __forceinline__ void conv_B(const float* __restrict__ Wk,
                                       char* dst_hi, char* dst_lo, int tid) {
    const int o = tid >> 2, i0 = (tid & 3) * 16;
    const float4* wr = (const float4*)(Wk + o * 64 + i0);
    uint32_t h[8], l[8];
    #pragma unroll
    for (int u = 0; u < 4; ++u) {
        float4 q = wr[u];
        uint32_t h0 = cvt2(q.x, q.y);
        uint32_t h1 = cvt2(q.z, q.w);
        h[u * 2 + 0] = h0;
        h[u * 2 + 1] = h1;
        l[u * 2 + 0] = cvt2(q.x - lo16f(h0), q.y - hi16f(h0));
        l[u * 2 + 1] = cvt2(q.z - lo16f(h1), q.w - hi16f(h1));
    }
    uint32_t off0 = SW128((uint32_t)(o * 128 + i0 * 2));
    uint32_t off1 = SW128((uint32_t)(o * 128 + i0 * 2 + 16));
    *(uint4*)(dst_hi + off0) = make_uint4(h[0], h[1], h[2], h[3]);
    *(uint4*)(dst_hi + off1) = make_uint4(h[4], h[5], h[6], h[7]);
    *(uint4*)(dst_lo + off0) = make_uint4(l[0], l[1], l[2], l[3]);
    *(uint4*)(dst_lo + off1) = make_uint4(l[4], l[5], l[6], l[7]);
}

// ---------------------------------------------------------------------------
// Warp-level: D[16 x 64] = Xrow[16 rows] @ W^T via 3-product bf16 split.
// ---------------------------------------------------------------------------
__device__ __forceinline__ void mma_rows16(
    const float* __restrict__ Xrow, uint32_t sb_hi, uint32_t sb_lo,
    int lane, float D[8][4])
{
    const int g = lane >> 2, t2 = (lane & 3) * 2;
    const int brow = ((lane >> 4) & 1) * 8 + (lane & 7);
    const int bcho = (lane >> 3) & 1;

    float2 f[4][4];
    {
        const float* r0b = Xrow + (size_t)g * F + t2;
        const float* r1b = r0b + 8 * F;
        #pragma unroll
        for (int s = 0; s < 4; ++s) {
            f[s][0] = *(const float2*)(r0b + s * 16);
            f[s][1] = *(const float2*)(r1b + s * 16);
            f[s][2] = *(const float2*)(r0b + s * 16 + 8);
            f[s][3] = *(const float2*)(r1b + s * 16 + 8);
        }
    }
    uint32_t ah[4][4], al[4][4];
    #pragma unroll
    for (int s = 0; s < 4; ++s)
        #pragma unroll
        for (int q = 0; q < 4; ++q) {
            uint32_t h = cvt2(f[s][q].x, f[s][q].y);
            ah[s][q] = h;
            al[s][q] = cvt2(f[s][q].x - lo16f(h), f[s][q].y - hi16f(h));
        }

    #pragma unroll
    for (int nt = 0; nt < 8; ++nt)
        #pragma unroll
        for (int r = 0; r < 4; ++r) D[nt][r] = 0.f;

    #pragma unroll
    for (int s = 0; s < 4; ++s) {
        #pragma unroll
        for (int np = 0; np < 4; ++np) {
            uint32_t boff = SW128((uint32_t)((np * 16 + brow) * 128 + (2 * s + bcho) * 16));
            uint32_t bh[4], bl[4];
            ldsm4(sb_hi + boff, bh[0], bh[1], bh[2], bh[3]);
            ldsm4(sb_lo + boff, bl[0], bl[1], bl[2], bl[3]);
            mma16816(D[np * 2 + 0], ah[s], bh[0], bh[1]);
            mma16816(D[np * 2 + 0], al[s], bh[0], bh[1]);
            mma16816(D[np * 2 + 0], ah[s], bl[0], bl[1]);
            mma16816(D[np * 2 + 1], ah[s], bh[2], bh[3]);
            mma16816(D[np * 2 + 1], al[s], bh[2], bh[3]);
            mma16816(D[np * 2 + 1], ah[s], bl[2], bl[3]);
        }
    }
}

// ---------------------------------------------------------------------------
// Y producer (persistent): CTAs [0,296) HMMA tiles k=3..7 (31*32 = 992 jobs);
// CTAs [296,328) scalar small levels k=8..14.
// ---------------------------------------------------------------------------
__global__ __launch_bounds__(256, 2) void heap_mm_Y(
    const float* __restrict__ X, const float* __restrict__ W,
    const float* __restrict__ Bv)
{
    __shared__ char smem[SM_B_TOTAL];
    const int tid = threadIdx.x;
    const int lane = tid & 31, warp = tid >> 5;
    const uint32_t sbase = smem_u32(smem);

    if (blockIdx.x < YGRID_HMMA) {
        const int J = 31 * 32, CH = (J + YGRID_HMMA - 1) / YGRID_HMMA;  // 4
        const int e0 = blockIdx.x * CH;
        const int e1 = min(e0 + CH, J);
        int prevk = -1;
        for (int e = e0; e < e1; ++e) {
            const int b = e & 31;
            int rem = e >> 5, k = 3, nt = 16;          // tiles/level: 16,8,...,1
            while (rem >= nt) { rem -= nt; nt >>= 1; ++k; }
            const int a0 = rem * 128;

            if (k != prevk) {
                __syncthreads();
                conv_B(W + (size_t)k * F * F, smem + SM_BHI, smem + SM_BLO, tid);
                __syncthreads();
                prevk = k;
            }

            float D[8][4];
            mma_rows16(X + ((size_t)b * NODES + a0 + warp * 16) * F,
                       sbase + SM_BHI, sbase + SM_BLO, lane, D);

            const int gg = lane >> 2, t2 = (lane & 3) * 2;
            const int r0 = a0 + warp * 16 + gg;
            const float* bias = Bv + k * F;
            float* yg = g_Y + YOFF(k) * (BATCH * F) + ((size_t)b * (NODES >> k)) * F;
            #pragma unroll
            for (int ntl = 0; ntl < 8; ++ntl) {
                const int c = ntl * 8 + t2;
                const float b0 = bias[c], b1 = bias[c + 1];
                *(float2*)(yg + (size_t)r0 * F + c) =
                    make_float2(D[ntl][0] + b0, D[ntl][1] + b1);
                *(float2*)(yg + (size_t)(r0 + 8) * F + c) =
                    make_float2(D[ntl][2] + b0, D[ntl][3] + b1);
            }
        }
    } else {
        // small levels k = 8..14: 224 jobs over 32 CTAs (7 each)
        __shared__ float ws[64 * 64];
        const int o = tid & 63, rg = tid >> 6;
        const int bx = blockIdx.x - YGRID_HMMA;
        int prevk = -1;
        for (int e = bx * 7; e < min(bx * 7 + 7, 224); ++e) {
            const int k = 8 + (e >> 5);
            const int b = e & 31;
            const int n = NODES >> k;
            if (k != prevk) {
                __syncthreads();
                const float* wk = W + (size_t)k * F * F;
                for (int idx = tid; idx < F * F; idx += 256)
                    ws[(idx & 63) * 64 + (idx >> 6)] = wk[idx];
                __syncthreads();
                prevk = k;
            }
            float* yg = g_Y + YOFF(k) * (BATCH * F) + (size_t)b * n * F;
            for (int a = rg; a < n; a += 4) {
                const float* Xb = X + ((size_t)b * NODES + a) * F;
                float s0 = 0.f, s1 = 0.f, s2 = 0.f, s3 = 0.f;
                #pragma unroll
                for (int i = 0; i < 64; i += 4) {
                    s0 = fmaf(__ldg(Xb + i + 0), ws[(i + 0) * 64 + o], s0);
                    s1 = fmaf(__ldg(Xb + i + 1), ws[(i + 1) * 64 + o], s1);
                    s2 = fmaf(__ldg(Xb + i + 2), ws[(i + 2) * 64 + o], s2);
                    s3 = fmaf(__ldg(Xb + i + 3), ws[(i + 3) * 64 + o], s3);
                }
                yg[(size_t)a * F + o] = Bv[k * F + o] + ((s0 + s1) + (s2 + s3));
            }
        }
    }
}

// ---------------------------------------------------------------------------
// Final (persistent, Y1+Y2 fused, G3 gather warp-specialized):
//   warps 0-3: Y1s[0..63]  = X[p0+..] @ W1^T + b1      (p0 = a0>>1)
//   warps 4-5: Y2s[0..31]  = X[q0+..] @ W2^T + b2      (q0 = a0>>2)
//   warps 6-7: G3s[0..15]  = sum_{kp<=level(r)} Y_{kp+3}[r>>kp]  (r0 = a0>>3)
//   all warps: D0 = X[a0+..] @ W0^T
//   out[j] = D0 + b0 + [j>=1]Y1s[j>>1] + [j>=2]Y2s[j>>2] + [j>=4]G3s[j>>3]
// ---------------------------------------------------------------------------
__global__ __launch_bounds__(256, 2) void heap_mm_final(
    const float* __restrict__ X, const float* __restrict__ W,
    const float* __restrict__ Bv, float* __restrict__ out)
{
    extern __shared__ char dsm[];
    float* Y1s = (float*)(dsm + FY1S);
    float* Y2s = (float*)(dsm + FY2S);
    float* G3s = (float*)(dsm + FG3S);
    const int tid = threadIdx.x;
    const int lane = tid & 31, warp = tid >> 5;
    const uint32_t sbase = smem_u32(dsm);

    conv_B(W,        dsm + FB0HI, dsm + FB0LO, tid);
    conv_B(W + 4096, dsm + FB1HI, dsm + FB1LO, tid);
    conv_B(W + 8192, dsm + FB2HI, dsm + FB2LO, tid);

    const int J = 128 * 32, CH = (J + FGRID - 1) / FGRID;   // 14
    const int e0 = blockIdx.x * CH;
    const int e1 = min(e0 + CH, J);

    for (int e = e0; e < e1; ++e) {
        const int b = e >> 7;            // batch major
        const int a0 = (e & 127) * 128;  // consecutive tiles within batch
        const int p0 = a0 >> 1;
        const int q0 = a0 >> 2;
        const int r0 = a0 >> 3;

        __syncthreads();   // stage buffers free; B images ready (1st iter)

        if (warp < 4) {
            // ---- Y1 tile: rows p0 + warp*16 .. +15 with W1 ----
            float D1[8][4];
            mma_rows16(X + ((size_t)b * NODES + p0 + warp * 16) * F,
                       sbase + FB1HI, sbase + FB1LO, lane, D1);
            const int gg = lane >> 2, t2 = (lane & 3) * 2;
            const int lr = warp * 16 + gg;
            const float* b1v = Bv + F;
            #pragma unroll
            for (int ntl = 0; ntl < 8; ++ntl) {
                const int c = ntl * 8 + t2;
                const float b0 = b1v[c], b1 = b1v[c + 1];
                *(float2*)(Y1s + lr * P + c) =
                    make_float2(D1[ntl][0] + b0, D1[ntl][1] + b1);
                *(float2*)(Y1s + (lr + 8) * P + c) =
                    make_float2(D1[ntl][2] + b0, D1[ntl][3] + b1);
            }
        } else if (warp < 6) {
            // ---- Y2 tile: rows q0 + (warp-4)*16 .. +15 with W2 ----
            float D2[8][4];
            mma_rows16(X + ((size_t)b * NODES + q0 + (warp - 4) * 16) * F,
                       sbase + FB2HI, sbase + FB2LO, lane, D2);
            const int gg = lane >> 2, t2 = (lane & 3) * 2;
            const int lr = (warp - 4) * 16 + gg;
            const float* b2v = Bv + 2 * F;
            #pragma unroll
            for (int ntl = 0; ntl < 8; ++ntl) {
                const int c = ntl * 8 + t2;
                const float b0 = b2v[c], b1 = b2v[c + 1];
                *(float2*)(Y2s + lr * P + c) =
                    make_float2(D2[ntl][0] + b0, D2[ntl][1] + b1);
                *(float2*)(Y2s + (lr + 8) * P + c) =
                    make_float2(D2[ntl][2] + b0, D2[ntl][3] + b1);
            }
        } else {
            // ---- G3 gather: 16 r rows x 4 quarters over 64 threads ----
            const int t3 = tid - 192;          // 0..63
            const int rl = t3 >> 2;
            const int r = r0 + rl;
            const int fq = (t3 & 3) * 16;
            const int level = r ? (32 - __clz((unsigned)r)) : 0;

            float4 a0v = make_float4(0.f, 0.f, 0.f, 0.f);
            float4 a1v = a0v, a2v = a0v, a3v = a0v;
            #pragma unroll
            for (int kp = 0; kp < 12; ++kp) {
                if (level >= kp) {
                    const int kk = kp + 3;
                    const float4* src = (const float4*)(
                        g_Y + YOFF(kk) * (BATCH * F)
                            + ((size_t)b * (NODES >> kk) + (r >> kp)) * F + fq);
                    float4 s0 = src[0], s1 = src[1], s2 = src[2], s3 = src[3];
                    a0v.x += s0.x; a0v.y += s0.y; a0v.z += s0.z; a0v.w += s0.w;
                    a1v.x += s1.x; a1v.y += s1.y; a1v.z += s1.z; a1v.w += s1.w;
                    a2v.x += s2.x; a2v.y += s2.y; a2v.z += s2.z; a2v.w += s2.w;
                    a3v.x += s3.x; a3v.y += s3.y; a3v.z += s3.z; a3v.w += s3.w;
                }
            }
            float4* gd = (float4*)(G3s + rl * P + fq);
            gd[0] = a0v; gd[1] = a1v; gd[2] = a2v; gd[3] = a3v;
        }

        // ---- main tile with W0 (all warps) ----
        float D0[8][4];
        mma_rows16(X + ((size_t)b * NODES + a0 + warp * 16) * F,
                   sbase + FB0HI, sbase + FB0LO, lane, D0);

        __syncthreads();   // stage buffers complete

        const int gg = lane >> 2, t2 = (lane & 3) * 2;
        const int j0 = a0 + warp * 16 + gg;
        const int lr = warp * 16 + gg;
        const int l1a = lr >> 1, l1b = (lr + 8) >> 1;
        const int l2a = lr >> 2, l2b = (lr + 8) >> 2;
        const int l3a = lr >> 3, l3b = (lr + 8) >> 3;
        float* ob = out + (size_t)b * NODES * F;

        #pragma unroll
        for (int ntl = 0; ntl < 8; ++ntl) {
            const int c = ntl * 8 + t2;
            const float b0 = Bv[c], b1 = Bv[c + 1];
            {   // row j0
                float v0 = D0[ntl][0] + b0, v1 = D0[ntl][1] + b1;
                if (j0 >= 1) { v0 += Y1s[l1a * P + c]; v1 += Y1s[l1a * P + c + 1]; }
                if (j0 >= 2) { v0 += Y2s[l2a * P + c]; v1 += Y2s[l2a * P + c + 1]; }
                if (j0 >= 4) { v0 += G3s[l3a * P + c]; v1 += G3s[l3a * P + c + 1]; }
                *(float2*)(ob + (size_t)j0 * F + c) = make_float2(v0, v1);
            }
            {   // row j0 + 8 (>= 8 -> all terms apply)
                *(float2*)(ob + (size_t)(j0 + 8) * F + c) =
                    make_float2(D0[ntl][2] + b0 + Y1s[l1b * P + c]
                                + Y2s[l2b * P + c] + G3s[l3b * P + c],
                                D0[ntl][3] + b1 + Y1s[l1b * P + c + 1]
                                + Y2s[l2b * P + c + 1] + G3s[l3b * P + c + 1]);
            }
        }
    }
}

// ---------------------------------------------------------------------------
extern "C" void kernel_launch(void* const* d_in, const int* in_sizes, int n_in,
                              void* d_out, int out_size) {
    const float* X  = (const float*)d_in[0];   // [32, 16384, 64]
    const float* W  = (const float*)d_in[1];   // [15, 64, 64]
    const float* Bv = (const float*)d_in[2];   // [15, 64]
    float* out = (float*)d_out;                // [32, 16384, 64]

    cudaFuncSetAttribute(heap_mm_final,
                         cudaFuncAttributeMaxDynamicSharedMemorySize, SMF_TOTAL);

    heap_mm_Y     <<<YGRID, 256>>>(X, W, Bv);
    heap_mm_final <<<FGRID, 256, SMF_TOTAL>>>(X, W, Bv, out);
}

// round 12
// speedup vs baseline: 3.1203x; 1.0487x over previous
#include <cuda_runtime.h>
#include <cuda_bf16.h>
#include <cstdint>

#define NODES 16384
#define BATCH 32
#define F 64

typedef unsigned long long ull;

// Y_k for k=3..14 (level k starts at row YOFF(k); k<3 unused).
__device__ float g_Y[(size_t)16383 * BATCH * F];

__host__ __device__ constexpr size_t YOFF(int k) {   // k >= 1
    return (size_t)(16384 - (16384 >> (k - 1)));
}

#define SW128(x) ((x) ^ (((x) >> 3) & 0x70))

// ---- final kernel dynamic smem layout (bytes) ----
#define FB0HI 0
#define FB0LO 8192
#define FB1HI 16384
#define FB1LO 24576
#define FB2HI 32768
#define FB2LO 40960
#define FSTG  49152                 // stage region: 8 segs x 4352 = 34816
#define SEG   4352                  // per-warp seg: A hi @0 (2KB), A lo @2176 (2KB)
                                    // doubles as out-stage rows w*16.. (pitch 272B)
#define FY1S  (FSTG + 8 * SEG)      // 83968: 64 x 68 fp32
#define FY2S  (FY1S + 17408)        // 32 x 68 fp32
#define FG3S  (FY2S + 8704)         // 16 x 68 fp32
#define SMF_TOTAL (FG3S + 4352)     // 114432
#define P 68                        // stage pitch in floats (272 B)

// ---- Y kernel dynamic smem ----
#define YB_HI 0
#define YB_LO 8192
#define YSTG  16384
#define SMY_TOTAL (YSTG + 8 * SEG)  // 51200

#define FGRID 296
#define YGRID_HMMA 296
#define YGRID_SMALL 32
#define YGRID (YGRID_HMMA + YGRID_SMALL)

// ---------------- helpers ----------------
__device__ __forceinline__ uint32_t smem_u32(const void* p) {
    uint32_t a;
    asm("{ .reg .u64 t; cvta.to.shared.u64 t, %1; cvt.u32.u64 %0, t; }" : "=r"(a) : "l"(p));
    return a;
}
// pack: low half = lo, high half = hi
__device__ __forceinline__ uint32_t cvt2(float lo, float hi) {
    uint32_t r; asm("cvt.rn.bf16x2.f32 %0, %1, %2;" : "=r"(r) : "f"(hi), "f"(lo)); return r;
}
__device__ __forceinline__ float lo16f(uint32_t u) { return __uint_as_float(u << 16); }
__device__ __forceinline__ float hi16f(uint32_t u) { return __uint_as_float(u & 0xffff0000u); }

__device__ __forceinline__ void ldsm4(uint32_t a, uint32_t& r0, uint32_t& r1,
                                      uint32_t& r2, uint32_t& r3) {
    asm volatile("ldmatrix.sync.aligned.m8n8.x4.shared.b16 {%0,%1,%2,%3}, [%4];"
                 : "=r"(r0), "=r"(r1), "=r"(r2), "=r"(r3) : "r"(a) : "memory");
}
__device__ __forceinline__ void mma16816(float* d, const uint32_t* a,
                                         uint32_t b0, uint32_t b1) {
    asm volatile(
        "mma.sync.aligned.m16n8k16.row.col.f32.bf16.bf16.f32 "
        "{%0,%1,%2,%3}, {%4,%5,%6,%7}, {%8,%9}, {%0,%1,%2,%3};"
        : "+f"(d[0]), "+f"(d[1]), "+f"(d[2]), "+f"(d[3])
        : "r"(a[0]), "r"(a[1]), "r"(a[2]), "r"(a[3]), "r"(b0), "r"(b1));
}

// Convert one 64x64 fp32 W level into swizzled bf16 hi/lo smem images (256 thr).
__device__ __forceinline__ void conv_B(const float* __restrict__ Wk,
                                       char* dst_hi, char* dst_lo, int tid) {
    const int o = tid >> 2, i0 = (tid & 3) * 16;
    const float4* wr = (const float4*)(Wk + o * 64 + i0);
    uint32_t h[8], l[8];
    #pragma unroll
    for (int u = 0; u < 4; ++u) {
        float4 q = wr[u];
        uint32_t h0 = cvt2(q.x, q.y);
        uint32_t h1 = cvt2(q.z, q.w);
        h[u * 2 + 0] = h0;
        h[u * 2 + 1] = h1;
        l[u * 2 + 0] = cvt2(q.x - lo16f(h0), q.y - hi16f(h0));
        l[u * 2 + 1] = cvt2(q.z - lo16f(h1), q.w - hi16f(h1));
    }
    uint32_t off0 = SW128((uint32_t)(o * 128 + i0 * 2));
    uint32_t off1 = SW128((uint32_t)(o * 128 + i0 * 2 + 16));
    *(uint4*)(dst_hi + off0) = make_uint4(h[0], h[1], h[2], h[3]);
    *(uint4*)(dst_hi + off1) = make_uint4(h[4], h[5], h[6], h[7]);
    *(uint4*)(dst_lo + off0) = make_uint4(l[0], l[1], l[2], l[3]);
    *(uint4*)(dst_lo + off1) = make_uint4(l[4], l[5], l[6], l[7]);
}

// ---------------------------------------------------------------------------
// Stage 16 X rows (fp32) into this warp's smem seg as swizzled bf16 hi/lo via
// coalesced LDG.128, then ldmatrix the A fragments for all 4 k-chunks.
// ---------------------------------------------------------------------------
__device__ __forceinline__ void stage_A_frags(
    const float* __restrict__ Xrow,           // first of 16 rows
    char* segp, uint32_t sseg, int lane,
    uint32_t ah[4][4], uint32_t al[4][4])
{
    const int r = lane >> 4;            // 0/1
    const int c4 = lane & 15;           // float4 index within row
    float4 q[8];
    #pragma unroll
    for (int i = 0; i < 8; ++i)
        q[i] = *(const float4*)(Xrow + (size_t)(i * 2 + r) * F + c4 * 4);

    __syncwarp();                       // seg free (prev use done warp-wide)
    #pragma unroll
    for (int i = 0; i < 8; ++i) {
        uint32_t h0 = cvt2(q[i].x, q[i].y);
        uint32_t h1 = cvt2(q[i].z, q[i].w);
        uint32_t l0 = cvt2(q[i].x - lo16f(h0), q[i].y - hi16f(h0));
        uint32_t l1 = cvt2(q[i].z - lo16f(h1), q[i].w - hi16f(h1));
        uint32_t off = SW128((uint32_t)((i * 2 + r) * 128 + c4 * 8));
        *(ull*)(segp + off)        = (ull)h0 | ((ull)h1 << 32);
        *(ull*)(segp + 2176 + off) = (ull)l0 | ((ull)l1 << 32);
    }
    __syncwarp();

    const int arow = ((lane >> 3) & 1) * 8 + (lane & 7);
    const int acho = (lane >> 4) & 1;
    #pragma unroll
    for (int s = 0; s < 4; ++s) {
        uint32_t off = SW128((uint32_t)(arow * 128 + (2 * s + acho) * 16));
        ldsm4(sseg + off,        ah[s][0], ah[s][1], ah[s][2], ah[s][3]);
        ldsm4(sseg + 2176 + off, al[s][0], al[s][1], al[s][2], al[s][3]);
    }
    __syncwarp();
}

// MMA from prebuilt A fragments against B images (hi/lo), 3-product split.
__device__ __forceinline__ void mma_from_frags(
    const uint32_t ah[4][4], const uint32_t al[4][4],
    uint32_t sb_hi, uint32_t sb_lo, int lane, float D[8][4])
{
    const int brow = ((lane >> 4) & 1) * 8 + (lane & 7);
    const int bcho = (lane >> 3) & 1;

    #pragma unroll
    for (int nt = 0; nt < 8; ++nt)
        #pragma unroll
        for (int rr = 0; rr < 4; ++rr) D[nt][rr] = 0.f;

    #pragma unroll
    for (int s = 0; s < 4; ++s) {
        #pragma unroll
        for (int np = 0; np < 4; ++np) {
            uint32_t boff = SW128((uint32_t)((np * 16 + brow) * 128 + (2 * s + bcho) * 16));
            uint32_t bh[4], bl[4];
            ldsm4(sb_hi + boff, bh[0], bh[1], bh[2], bh[3]);
            ldsm4(sb_lo + boff, bl[0], bl[1], bl[2], bl[3]);
            mma16816(D[np * 2 + 0], ah[s], bh[0], bh[1]);
            mma16816(D[np * 2 + 0], al[s], bh[0], bh[1]);
            mma16816(D[np * 2 + 0], ah[s], bl[0], bl[1]);
            mma16816(D[np * 2 + 1], ah[s], bh[2], bh[3]);
            mma16816(D[np * 2 + 1], al[s], bh[2], bh[3]);
            mma16816(D[np * 2 + 1], ah[s], bl[2], bl[3]);
        }
    }
}

// Store a warp's 16-row D tile into its stage seg (fp32, pitch P floats).
__device__ __forceinline__ void stage_D(float* seg, const float D[8][4],
                                        int lane, const float* bias /*or null*/)
{
    const int gg = lane >> 2, t2 = (lane & 3) * 2;
    #pragma unroll
    for (int ntl = 0; ntl < 8; ++ntl) {
        const int c = ntl * 8 + t2;
        float b0 = bias ? bias[c] : 0.f, b1 = bias ? bias[c + 1] : 0.f;
        *(float2*)(seg + gg * P + c)       = make_float2(D[ntl][0] + b0, D[ntl][1] + b1);
        *(float2*)(seg + (gg + 8) * P + c) = make_float2(D[ntl][2] + b0, D[ntl][3] + b1);
    }
}

// ---------------------------------------------------------------------------
// Y producer (persistent): CTAs [0,296) HMMA tiles k=3..7 (992 jobs);
// CTAs [296,328) scalar small levels k=8..14.
// ---------------------------------------------------------------------------
__global__ __launch_bounds__(256, 2) void heap_mm_Y(
    const float* __restrict__ X, const float* __restrict__ W,
    const float* __restrict__ Bv)
{
    extern __shared__ char dsm[];
    const int tid = threadIdx.x;
    const int lane = tid & 31, warp = tid >> 5;
    const uint32_t sbase = smem_u32(dsm);

    if (blockIdx.x < YGRID_HMMA) {
        char* segp = dsm + YSTG + warp * SEG;
        const uint32_t sseg = sbase + YSTG + warp * SEG;
        const int J = 31 * 32, CH = (J + YGRID_HMMA - 1) / YGRID_HMMA;  // 4
        const int e0 = blockIdx.x * CH;
        const int e1 = min(e0 + CH, J);
        int prevk = -1;
        for (int e = e0; e < e1; ++e) {
            const int b = e & 31;
            int rem = e >> 5, k = 3, nt = 16;
            while (rem >= nt) { rem -= nt; nt >>= 1; ++k; }
            const int a0 = rem * 128;

            if (k != prevk) {
                __syncthreads();
                conv_B(W + (size_t)k * F * F, dsm + YB_HI, dsm + YB_LO, tid);
                __syncthreads();
                prevk = k;
            }

            uint32_t ah[4][4], al[4][4];
            stage_A_frags(X + ((size_t)b * NODES + a0 + warp * 16) * F,
                          segp, sseg, lane, ah, al);
            float D[8][4];
            mma_from_frags(ah, al, sbase + YB_HI, sbase + YB_LO, lane, D);

            // stage D (fp32) then coalesced store to g_Y with bias
            float* seg = (float*)segp;
            stage_D(seg, D, lane, nullptr);
            __syncwarp();

            const int c4 = lane & 15;
            float4 bq = *(const float4*)(Bv + k * F + c4 * 4);
            float* yg = g_Y + YOFF(k) * (BATCH * F) + ((size_t)b * (NODES >> k)) * F;
            #pragma unroll
            for (int it = 0; it < 8; ++it) {
                const int rr = it * 2 + (lane >> 4);
                float4 v = *(const float4*)(seg + rr * P + c4 * 4);
                v.x += bq.x; v.y += bq.y; v.z += bq.z; v.w += bq.w;
                *(float4*)(yg + (size_t)(a0 + warp * 16 + rr) * F + c4 * 4) = v;
            }
            __syncwarp();
        }
    } else {
        // small levels k = 8..14: 224 jobs over 32 CTAs (7 each)
        float* ws = (float*)dsm;                      // 16KB overlay
        const int o = tid & 63, rg = tid >> 6;
        const int bx = blockIdx.x - YGRID_HMMA;
        int prevk = -1;
        for (int e = bx * 7; e < min(bx * 7 + 7, 224); ++e) {
            const int k = 8 + (e >> 5);
            const int b = e & 31;
            const int n = NODES >> k;
            if (k != prevk) {
                __syncthreads();
                const float* wk = W + (size_t)k * F * F;
                for (int idx = tid; idx < F * F; idx += 256)
                    ws[(idx & 63) * 64 + (idx >> 6)] = wk[idx];
                __syncthreads();
                prevk = k;
            }
            float* yg = g_Y + YOFF(k) * (BATCH * F) + (size_t)b * n * F;
            for (int a = rg; a < n; a += 4) {
                const float* Xb = X + ((size_t)b * NODES + a) * F;
                float s0 = 0.f, s1 = 0.f, s2 = 0.f, s3 = 0.f;
                #pragma unroll
                for (int i = 0; i < 64; i += 4) {
                    s0 = fmaf(__ldg(Xb + i + 0), ws[(i + 0) * 64 + o], s0);
                    s1 = fmaf(__ldg(Xb + i + 1), ws[(i + 1) * 64 + o], s1);
                    s2 = fmaf(__ldg(Xb + i + 2), ws[(i + 2) * 64 + o], s2);
                    s3 = fmaf(__ldg(Xb + i + 3), ws[(i + 3) * 64 + o], s3);
                }
                yg[(size_t)a * F + o] = Bv[k * F + o] + ((s0 + s1) + (s2 + s3));
            }
        }
    }
}

// ---------------------------------------------------------------------------
// Final (persistent, Y1+Y2 fused, G3 gather, fully staged I/O):
//   warps 0-3: Y1s = X[p0..] @ W1^T + b1 ; warps 4-5: Y2s = X[q0..] @ W2^T + b2
//   warps 6-7: G3s[r] = sum Y_{kp+3}[r>>kp]
//   all: D0 = X[a0..] @ W0^T -> stage -> coalesced merge (+b0 +Y1s +Y2s +G3s)
// ---------------------------------------------------------------------------
__global__ __launch_bounds__(256, 2) void heap_mm_final(
    const float* __restrict__ X, const float* __restrict__ W,
    const float* __restrict__ Bv, float* __restrict__ out)
{
    extern __shared__ char dsm[];
    const int tid = threadIdx.x;
    const int lane = tid & 31, warp = tid >> 5;
    const uint32_t sbase = smem_u32(dsm);
    char* segp = dsm + FSTG + warp * SEG;
    const uint32_t sseg = sbase + FSTG + warp * SEG;
    float* Y1s = (float*)(dsm + FY1S);
    float* Y2s = (float*)(dsm + FY2S);
    float* G3s = (float*)(dsm + FG3S);
    float* stage = (float*)(dsm + FSTG);     // 128 rows x P floats

    conv_B(W,        dsm + FB0HI, dsm + FB0LO, tid);
    conv_B(W + 4096, dsm + FB1HI, dsm + FB1LO, tid);
    conv_B(W + 8192, dsm + FB2HI, dsm + FB2LO, tid);

    const int J = 128 * 32, CH = (J + FGRID - 1) / FGRID;   // 14
    const int e0 = blockIdx.x * CH;
    const int e1 = min(e0 + CH, J);

    const int c4 = tid & 15;
    const float4 b0q = *(const float4*)(Bv + c4 * 4);

    for (int e = e0; e < e1; ++e) {
        const int b = e >> 7;
        const int a0 = (e & 127) * 128;
        const int p0 = a0 >> 1, q0 = a0 >> 2, r0 = a0 >> 3;

        __syncthreads();   // stage/Y1s/Y2s/G3s free; B images ready

        if (warp < 4) {
            uint32_t ah[4][4], al[4][4];
            stage_A_frags(X + ((size_t)b * NODES + p0 + warp * 16) * F,
                          segp, sseg, lane, ah, al);
            float D1[8][4];
            mma_from_frags(ah, al, sbase + FB1HI, sbase + FB1LO, lane, D1);
            stage_D(Y1s + warp * 16 * P, D1, lane, Bv + F);
        } else if (warp < 6) {
            uint32_t ah[4][4], al[4][4];
            stage_A_frags(X + ((size_t)b * NODES + q0 + (warp - 4) * 16) * F,
                          segp, sseg, lane, ah, al);
            float D2[8][4];
            mma_from_frags(ah, al, sbase + FB2HI, sbase + FB2LO, lane, D2);
            stage_D(Y2s + (warp - 4) * 16 * P, D2, lane, Bv + 2 * F);
        } else {
            const int t3 = tid - 192;
            const int rl = t3 >> 2;
            const int r = r0 + rl;
            const int fq = (t3 & 3) * 16;
            const int level = r ? (32 - __clz((unsigned)r)) : 0;
            float4 a0v = make_float4(0.f, 0.f, 0.f, 0.f);
            float4 a1v = a0v, a2v = a0v, a3v = a0v;
            #pragma unroll
            for (int kp = 0; kp < 12; ++kp) {
                if (level >= kp) {
                    const int kk = kp + 3;
                    const float4* src = (const float4*)(
                        g_Y + YOFF(kk) * (BATCH * F)
                            + ((size_t)b * (NODES >> kk) + (r >> kp)) * F + fq);
                    float4 s0 = src[0], s1 = src[1], s2 = src[2], s3 = src[3];
                    a0v.x += s0.x; a0v.y += s0.y; a0v.z += s0.z; a0v.w += s0.w;
                    a1v.x += s1.x; a1v.y += s1.y; a1v.z += s1.z; a1v.w += s1.w;
                    a2v.x += s2.x; a2v.y += s2.y; a2v.z += s2.z; a2v.w += s2.w;
                    a3v.x += s3.x; a3v.y += s3.y; a3v.z += s3.z; a3v.w += s3.w;
                }
            }
            float4* gd = (float4*)(G3s + rl * P + fq);
            gd[0] = a0v; gd[1] = a1v; gd[2] = a2v; gd[3] = a3v;
        }

        // ---- main tile W0 (all warps) ----
        {
            uint32_t ah[4][4], al[4][4];
            stage_A_frags(X + ((size_t)b * NODES + a0 + warp * 16) * F,
                          segp, sseg, lane, ah, al);
            float D0[8][4];
            mma_from_frags(ah, al, sbase + FB0HI, sbase + FB0LO, lane, D0);
            // stage into own seg region == rows warp*16.. of `stage`
            stage_D(stage + warp * 16 * P, D0, lane, nullptr);
        }
        __syncthreads();   // all stage buffers complete

        // ---- coalesced merge + store ----
        float* ob = out + ((size_t)b * NODES + a0) * F;
        #pragma unroll
        for (int it = 0; it < 8; ++it) {
            const int row = it * 16 + (tid >> 4);
            const int j = a0 + row;
            float4 v = *(const float4*)(stage + row * P + c4 * 4);
            v.x += b0q.x; v.y += b0q.y; v.z += b0q.z; v.w += b0q.w;
            if (j >= 1) {
                float4 y1 = *(const float4*)(Y1s + (row >> 1) * P + c4 * 4);
                v.x += y1.x; v.y += y1.y; v.z += y1.z; v.w += y1.w;
            }
            if (j >= 2) {
                float4 y2 = *(const float4*)(Y2s + (row >> 2) * P + c4 * 4);
                v.x += y2.x; v.y += y2.y; v.z += y2.z; v.w += y2.w;
            }
            if (j >= 4) {
                float4 g3 = *(const float4*)(G3s + (row >> 3) * P + c4 * 4);
                v.x += g3.x; v.y += g3.y; v.z += g3.z; v.w += g3.w;
            }
            *(float4*)(ob + (size_t)row * F + c4 * 4) = v;
        }
    }
}

// ---------------------------------------------------------------------------
extern "C" void kernel_launch(void* const* d_in, const int* in_sizes, int n_in,
                              void* d_out, int out_size) {
    const float* X  = (const float*)d_in[0];   // [32, 16384, 64]
    const float* W  = (const float*)d_in[1];   // [15, 64, 64]
    const float* Bv = (const float*)d_in[2];   // [15, 64]
    float* out = (float*)d_out;                // [32, 16384, 64]

    cudaFuncSetAttribute(heap_mm_Y,
                         cudaFuncAttributeMaxDynamicSharedMemorySize, SMY_TOTAL);
    cudaFuncSetAttribute(heap_mm_final,
                         cudaFuncAttributeMaxDynamicSharedMemorySize, SMF_TOTAL);

    heap_mm_Y     <<<YGRID, 256, SMY_TOTAL>>>(X, W, Bv);
    heap_mm_final <<<FGRID, 256, SMF_TOTAL>>>(X, W, Bv, out);
}